// round 12
// baseline (speedup 1.0000x reference)
#include <cuda_runtime.h>
#include <cstdint>
#include <cfloat>
#include <math.h>

#define BA 2
#define A_COEF (-0.75f)

__constant__ float c_mean[3] = {0.485f, 0.456f, 0.406f};
__constant__ float c_std[3]  = {0.229f, 0.224f, 0.225f};

// ---------------- scratch (static device memory) ----------------
// batch-4 layout: [q_b0, q_b1, k_b0, k_b1]
__device__ float    g_up   [4*3*320*320];
__device__ float    g_bufA [4*64*320*320];
__device__ float    g_bufB [4*64*320*320];
__device__ float    g_feat [4*16*80*80];
__device__ float    g_P    [4*144*6400];     // [0:2)=Pq, [2:4)=Pk
__device__ uint32_t g_Ph   [4*144*6400];     // tf32 hi
__device__ uint32_t g_Pl   [4*144*6400];     // tf32 lo
__device__ float    g_wT   [259776];
__device__ float    g_mv   [2*BA*6400];
__device__ int      g_mi   [2*BA*6400];

#define OFF_W1 0
#define OFF_W2 1728
#define OFF_W3 38592
#define OFF_W4 112320

__device__ __forceinline__ float cubicw(float d){
    d = fabsf(d);
    if (d <= 1.f) return ((A_COEF + 2.f)*d - (A_COEF + 3.f))*d*d + 1.f;
    if (d < 2.f)  return A_COEF*(((d - 5.f)*d + 8.f)*d - 4.f);
    return 0.f;
}

// ---------------- tf32 helpers ----------------
__device__ __forceinline__ void split_tf32(float x, uint32_t& hi, uint32_t& lo){
    uint32_t h;
    asm("cvt.rna.tf32.f32 %0, %1;" : "=r"(h) : "f"(x));
    float l = x - __uint_as_float(h);
    uint32_t lr;
    asm("cvt.rna.tf32.f32 %0, %1;" : "=r"(lr) : "f"(l));
    hi = h; lo = lr;
}

__device__ __forceinline__ void mma_tf32(float* c,
        uint32_t a0, uint32_t a1, uint32_t a2, uint32_t a3,
        uint32_t b0, uint32_t b1){
    asm volatile("mma.sync.aligned.m16n8k8.row.col.f32.tf32.tf32.f32 "
        "{%0,%1,%2,%3}, {%4,%5,%6,%7}, {%8,%9}, {%0,%1,%2,%3};"
        : "+f"(c[0]),"+f"(c[1]),"+f"(c[2]),"+f"(c[3])
        : "r"(a0),"r"(a1),"r"(a2),"r"(a3), "r"(b0),"r"(b1));
}

// ---------------- merged weight transpose: all 4 layers in one launch ----------------
__global__ void transw_all_kernel(const float* __restrict__ w1, const float* __restrict__ w2,
                                  const float* __restrict__ w3, const float* __restrict__ w4,
                                  float* __restrict__ wT){
    int t = blockIdx.x*blockDim.x + threadIdx.x;
    if (t >= 259776) return;
    const float* w; int CO, CI, base;
    if (t < 38592){
        if (t < 1728){ w = w1; CO = 64;  CI = 3;   base = OFF_W1; }
        else         { w = w2; CO = 64;  CI = 64;  base = OFF_W2; }
    } else {
        if (t < 112320){ w = w3; CO = 128; CI = 64;  base = OFF_W3; }
        else           { w = w4; CO = 128; CI = 128; base = OFF_W4; }
    }
    int loc = t - base;
    int co  = loc / (CI*9);
    int r   = loc - co*(CI*9);
    wT[base + r*CO + co] = w[loc];
}

// ---------------- P tf32 pre-split ----------------
__global__ void psplit_kernel(const float* __restrict__ P, uint32_t* __restrict__ Ph,
                              uint32_t* __restrict__ Pl){
    int t = blockIdx.x*blockDim.x + threadIdx.x;
    if (t >= 4*144*6400) return;
    uint32_t h, l;
    split_tf32(P[t], h, l);
    Ph[t] = h; Pl[t] = l;
}

// ---------------- maxpool 2x2 stride 2 ----------------
__global__ void maxpool2_kernel(const float* __restrict__ in, float* __restrict__ out,
                                int total, int H2, int W2){
    int t = blockIdx.x*blockDim.x + threadIdx.x;
    if (t >= total) return;
    int x  = t % W2;
    int y  = (t / W2) % H2;
    int bc = t / (W2*H2);
    const float* p = in + (((size_t)bc*(H2*2)) + y*2)*(W2*2) + x*2;
    out[t] = fmaxf(fmaxf(p[0], p[1]), fmaxf(p[W2*2], p[W2*2+1]));
}

// ---------------- merged: sub_mean + bicubic upsample x2 for BOTH paths ----------------
__global__ void upsample_both_kernel(const float* __restrict__ query,
                                     const float* __restrict__ key,
                                     float* __restrict__ dst){
    const int HALF = BA*3*320*320;
    int t = blockIdx.x*blockDim.x + threadIdx.x;
    if (t >= 2*HALF) return;
    int path = t / HALF;
    int r    = t - path*HALF;
    int ox = r % 320;
    int oy = (r / 320) % 320;
    int c  = (r / (320*320)) % 3;
    int b  = r / (320*320*3);

    const int Hs = 160, Ws = 160;
    float sy = (float)((double)(Hs-1) / 319.0);
    float sx = (float)((double)(Ws-1) / 319.0);
    float cy = (float)oy * sy;
    float cx = (float)ox * sx;
    float fy = floorf(cy), fx = floorf(cx);
    float tv = cy - fy,    tu = cx - fx;
    int iy = (int)fy, ix = (int)fx;

    float wy[4] = {cubicw(tv+1.f), cubicw(tv), cubicw(tv-1.f), cubicw(tv-2.f)};
    float wx[4] = {cubicw(tu+1.f), cubicw(tu), cubicw(tu-1.f), cubicw(tu-2.f)};

    float mean = c_mean[c], stdv = c_std[c];
    const float* qp = query + ((size_t)b*3 + c)*Hs*Ws;
    const float* kp = key   + ((size_t)b*3 + c)*320*320;

    float acc = 0.f;
    #pragma unroll
    for (int j = 0; j < 4; j++){
        int xx = ix - 1 + j;
        xx = xx < 0 ? 0 : (xx > Ws-1 ? Ws-1 : xx);
        float colsum = 0.f;
        #pragma unroll
        for (int i = 0; i < 4; i++){
            int yy = iy - 1 + i;
            yy = yy < 0 ? 0 : (yy > Hs-1 ? Hs-1 : yy);
            float s;
            if (path == 0){
                s = qp[yy*Ws + xx];
            } else {
                const float* p = kp + (yy*2)*320 + xx*2;
                s = (p[0] + p[1] + p[320] + p[321]) / 4.0f;
            }
            float v = (s - mean) / stdv;
            colsum += wy[i]*v;
        }
        acc += wx[j]*colsum;
    }
    dst[(size_t)path*HALF + r] = acc;
}

// ---------------- conv3x3 FFMA (used only for CI=3 first layer) ----------------
__global__ __launch_bounds__(256)
void conv3x3_kernel(const float* __restrict__ in, const float* __restrict__ wT,
                    const float* __restrict__ bias, float* __restrict__ out,
                    int CI, int CO, int H, int W){
    __shared__ float insm[8*4*72];
    __shared__ float wsm [72*64];

    int tid = threadIdx.x;
    int tx = tid & 15;
    int ty = tid >> 4;
    int x0 = blockIdx.x * 64;
    int y0 = blockIdx.y * 2;
    int cog = CO >> 6;
    int b   = blockIdx.z / cog;
    int co0 = (blockIdx.z % cog) << 6;

    float acc[4][2][4];
    #pragma unroll
    for (int i = 0; i < 4; i++)
        #pragma unroll
        for (int r = 0; r < 2; r++)
            #pragma unroll
            for (int j = 0; j < 4; j++) acc[i][r][j] = 0.f;

    const float* inb = in + (size_t)b*CI*H*W;

    for (int ci0 = 0; ci0 < CI; ci0 += 8){
        int cn = CI - ci0; if (cn > 8) cn = 8;
        __syncthreads();
        int nin = cn*264;
        for (int s = tid; s < nin; s += 256){
            int ci  = s / 264;
            int rem = s - ci*264;
            int r   = rem / 66;
            int xx  = rem - r*66;
            int gy = y0 + r - 1;
            int gx = x0 + xx - 1;
            float v = 0.f;
            if (gy >= 0 && gy < H && gx >= 0 && gx < W)
                v = inb[((size_t)(ci0+ci)*H + gy)*W + gx];
            insm[(ci*4 + r)*72 + xx] = v;
        }
        int kk = cn*9;
        for (int s = tid; s < kk*64; s += 256){
            int k  = s >> 6;
            int co = s & 63;
            wsm[k*64 + co] = wT[((size_t)ci0*9 + k)*CO + co0 + co];
        }
        __syncthreads();

        float accc[4][2][4];
        #pragma unroll
        for (int i = 0; i < 4; i++)
            #pragma unroll
            for (int r = 0; r < 2; r++)
                #pragma unroll
                for (int j = 0; j < 4; j++) accc[i][r][j] = 0.f;

        for (int ci = 0; ci < cn; ci++){
            #pragma unroll
            for (int dy = 0; dy < 3; dy++){
                const float* ipa = &insm[(ci*4 + dy)*72 + tx*4];
                float a6[6], b6[6];
                #pragma unroll
                for (int u = 0; u < 6; u++){ a6[u] = ipa[u]; b6[u] = ipa[72+u]; }
                #pragma unroll
                for (int dx = 0; dx < 3; dx++){
                    float4 wv = *(const float4*)&wsm[(ci*9 + dy*3 + dx)*64 + ty*4];
                    #pragma unroll
                    for (int j = 0; j < 4; j++){
                        float ia = a6[dx + j];
                        float ib = b6[dx + j];
                        accc[0][0][j] += wv.x * ia;  accc[0][1][j] += wv.x * ib;
                        accc[1][0][j] += wv.y * ia;  accc[1][1][j] += wv.y * ib;
                        accc[2][0][j] += wv.z * ia;  accc[2][1][j] += wv.z * ib;
                        accc[3][0][j] += wv.w * ia;  accc[3][1][j] += wv.w * ib;
                    }
                }
            }
        }
        #pragma unroll
        for (int i = 0; i < 4; i++)
            #pragma unroll
            for (int r = 0; r < 2; r++)
                #pragma unroll
                for (int j = 0; j < 4; j++) acc[i][r][j] += accc[i][r][j];
    }

    #pragma unroll
    for (int i = 0; i < 4; i++){
        int co = co0 + ty*4 + i;
        float bv = bias[co];
        #pragma unroll
        for (int r = 0; r < 2; r++){
            #pragma unroll
            for (int j = 0; j < 4; j++){
                int x = x0 + tx*4 + j;
                if (x < W){
                    float v = acc[i][r][j] + bv;
                    out[(((size_t)b*CO + co)*H + (y0+r))*W + x] = fmaxf(v, 0.f);
                }
            }
        }
    }
}

// ---------------- conv3x3 via 3xTF32 tensor-core implicit GEMM, 1 row/block ----------------
// block: 64 co x 80 px x 1 row; 8 warps = 4(co) x 2(px); warp tile 16co x 40px.
// __launch_bounds__(256,3): cap regs at 85 -> 3 CTAs/SM (occupancy 24% -> 37.5%).
__global__ __launch_bounds__(256, 3)
void conv3x3_tf32_kernel(const float* __restrict__ in, const float* __restrict__ wT,
                         const float* __restrict__ bias, float* __restrict__ out,
                         int CI, int CO, int H, int W){
    __shared__ float ismh[8*3*84];
    __shared__ float isml[8*3*84];
    __shared__ float wsm [9*8*65];

    int tid  = threadIdx.x;
    int warp = tid >> 5, lane = tid & 31;
    int wm = warp & 3;
    int wn = warp >> 2;
    int g  = lane >> 2;
    int q  = lane & 3;

    int x0 = blockIdx.x * 80;
    int y  = blockIdx.y;
    int cog = CO >> 6;
    int b   = blockIdx.z / cog;
    int co0 = (blockIdx.z % cog) << 6;

    const float* inb = in + (size_t)b*CI*H*W;

    float cacc[5][4];
    #pragma unroll
    for (int nt = 0; nt < 5; nt++)
        #pragma unroll
        for (int i = 0; i < 4; i++) cacc[nt][i] = 0.f;

    for (int ci0 = 0; ci0 < CI; ci0 += 8){
        __syncthreads();
        for (int s = tid; s < 8*3*82; s += 256){
            int ci  = s / 246;
            int rem = s - ci*246;
            int r   = rem / 82;
            int col = rem - r*82;
            int gy = y + r - 1;
            int gx = x0 + col - 1;
            float v = 0.f;
            if (gy >= 0 && gy < H && gx >= 0 && gx < W)
                v = inb[((size_t)(ci0+ci)*H + gy)*W + gx];
            uint32_t h, l;
            split_tf32(v, h, l);
            ismh[(ci*3 + r)*84 + col] = __uint_as_float(h);
            isml[(ci*3 + r)*84 + col] = __uint_as_float(l);
        }
        for (int s = tid; s < 9*8*64; s += 256){
            int tap = s >> 9;
            int rem = s & 511;
            int ci  = rem >> 6;
            int co  = rem & 63;
            wsm[(tap*8 + ci)*65 + co] = wT[((size_t)(ci0+ci)*9 + tap)*CO + co0 + co];
        }
        __syncthreads();

        #pragma unroll
        for (int dy = 0; dy < 3; dy++){
            #pragma unroll
            for (int dx = 0; dx < 3; dx++){
                int tap = dy*3 + dx;
                float a0 = wsm[(tap*8 + q  )*65 + wm*16 + g    ];
                float a1 = wsm[(tap*8 + q  )*65 + wm*16 + g + 8];
                float a2 = wsm[(tap*8 + q+4)*65 + wm*16 + g    ];
                float a3 = wsm[(tap*8 + q+4)*65 + wm*16 + g + 8];
                uint32_t ah0,al0,ah1,al1,ah2,al2,ah3,al3;
                split_tf32(a0, ah0, al0);
                split_tf32(a1, ah1, al1);
                split_tf32(a2, ah2, al2);
                split_tf32(a3, ah3, al3);
                #pragma unroll
                for (int nt = 0; nt < 5; nt++){
                    int col = wn*40 + nt*8 + g + dx;
                    int i0 = ( q   *3 + dy)*84 + col;
                    int i1 = ((q+4)*3 + dy)*84 + col;
                    uint32_t bh0 = __float_as_uint(ismh[i0]);
                    uint32_t bh1 = __float_as_uint(ismh[i1]);
                    uint32_t bl0 = __float_as_uint(isml[i0]);
                    uint32_t bl1 = __float_as_uint(isml[i1]);
                    mma_tf32(cacc[nt], al0,al1,al2,al3, bh0,bh1);
                    mma_tf32(cacc[nt], ah0,ah1,ah2,ah3, bl0,bl1);
                    mma_tf32(cacc[nt], ah0,ah1,ah2,ah3, bh0,bh1);
                }
            }
        }
    }

    int coA = co0 + wm*16 + g;
    int coB = coA + 8;
    float bvA = bias[coA], bvB = bias[coB];
    float* outA = out + (((size_t)b*CO + coA)*H + y)*W;
    float* outB = out + (((size_t)b*CO + coB)*H + y)*W;
    #pragma unroll
    for (int nt = 0; nt < 5; nt++){
        int x = x0 + wn*40 + nt*8 + 2*q;
        outA[x  ] = fmaxf(cacc[nt][0] + bvA, 0.f);
        outA[x+1] = fmaxf(cacc[nt][1] + bvA, 0.f);
        outB[x  ] = fmaxf(cacc[nt][2] + bvB, 0.f);
        outB[x+1] = fmaxf(cacc[nt][3] + bvB, 0.f);
    }
}

// ---------------- 1x1 map conv (128 -> 16) + LeakyReLU(0.2), B=4 ----------------
__global__ void conv1x1_leaky_kernel(const float* __restrict__ in, const float* __restrict__ w,
                                     const float* __restrict__ bias, float* __restrict__ out){
    int t = blockIdx.x*blockDim.x + threadIdx.x;
    if (t >= 4*16*6400) return;
    int px = t % 6400;
    int co = (t / 6400) % 16;
    int b  = t / (6400*16);
    const float* ip = in + (size_t)b*128*6400 + px;
    const float* wp = w + co*128;
    float s = 0.f;
    for (int c0 = 0; c0 < 128; c0 += 16){
        float sc = 0.f;
        #pragma unroll
        for (int ci = 0; ci < 16; ci++) sc += ip[(size_t)(c0+ci)*6400] * wp[c0+ci];
        s += sc;
    }
    s += bias[co];
    out[t] = s > 0.f ? s : 0.2f*s;
}

// ---------------- 3x3 unfold (reflect pad) + per-position L2 normalize, B=4 ----------------
__global__ void patches_norm_kernel(const float* __restrict__ f, float* __restrict__ P){
    int t = blockIdx.x*blockDim.x + threadIdx.x;
    if (t >= 4*6400) return;
    int m = t % 6400;
    int b = t / 6400;
    int y = m / 80, x = m % 80;
    int ry[3], rx[3];
    #pragma unroll
    for (int i = 0; i < 3; i++){
        int yy = y + i - 1; ry[i] = yy < 0 ? -yy : (yy > 79 ? 158 - yy : yy);
        int xx = x + i - 1; rx[i] = xx < 0 ? -xx : (xx > 79 ? 158 - xx : xx);
    }
    const float* fb = f + (size_t)b*16*6400;
    float ss = 0.f;
    for (int c = 0; c < 16; c++){
        const float* fc = fb + c*6400;
        float sc = 0.f;
        #pragma unroll
        for (int i = 0; i < 3; i++)
            #pragma unroll
            for (int j = 0; j < 3; j++){
                float v = fc[ry[i]*80 + rx[j]];
                sc += v*v;
            }
        ss += sc;
    }
    float nrm = fmaxf(sqrtf(ss), 1e-12f);
    float* Pb = P + (size_t)b*144*6400;
    for (int c = 0; c < 16; c++){
        const float* fc = fb + c*6400;
        #pragma unroll
        for (int i = 0; i < 3; i++)
            #pragma unroll
            for (int j = 0; j < 3; j++)
                Pb[(size_t)(c*9 + i*3 + j)*6400 + m] = fc[ry[i]*80 + rx[j]] / nrm;
    }
}

// ---------------- cosine-sim via 3xTF32 mma v2 + streaming max/argmax ----------------
#define QSTR 68
#define KSTR 132
__global__ __launch_bounds__(256)
void match_tf32_kernel(const uint32_t* __restrict__ Ph, const uint32_t* __restrict__ Pl,
                       float* __restrict__ mv, int* __restrict__ mi){
    extern __shared__ float dsm[];
    float* qh = dsm;                  // [144][QSTR]
    float* ql = qh + 144*QSTR;
    float* kh = ql + 144*QSTR;        // [16][KSTR]
    float* kl = kh + 16*KSTR;

    int b    = blockIdx.y;
    int half = blockIdx.z;
    int m0   = blockIdx.x * 64;
    int tid  = threadIdx.x;
    int warp = tid >> 5, lane = tid & 31;
    int kw = warp & 3;    // key 32-group
    int qw = warp >> 2;   // query 32-group
    int g  = lane >> 2;
    int q  = lane & 3;

    const uint32_t* Qhb = Ph + (size_t)b*144*6400;
    const uint32_t* Qlb = Pl + (size_t)b*144*6400;
    const uint32_t* Khb = Ph + (size_t)(2+b)*144*6400;
    const uint32_t* Klb = Pl + (size_t)(2+b)*144*6400;

    for (int s = tid; s < 144*64; s += 256){
        int c = s >> 6, mm = s & 63;
        qh[c*QSTR + mm] = __uint_as_float(Qhb[(size_t)c*6400 + m0 + mm]);
        ql[c*QSTR + mm] = __uint_as_float(Qlb[(size_t)c*6400 + m0 + mm]);
    }

    float bestv[8];
    int   besti[8];
    #pragma unroll
    for (int i = 0; i < 8; i++){ bestv[i] = -FLT_MAX; besti[i] = 0; }

    int lbeg = half*3200, lend = lbeg + 3200;
    for (int l0 = lbeg; l0 < lend; l0 += 128){
        float acc[2][4][4];
        #pragma unroll
        for (int mf = 0; mf < 2; mf++)
            #pragma unroll
            for (int nf = 0; nf < 4; nf++)
                #pragma unroll
                for (int i = 0; i < 4; i++) acc[mf][nf][i] = 0.f;

        for (int c0 = 0; c0 < 144; c0 += 16){
            __syncthreads();
            for (int s = tid; s < 16*128; s += 256){
                int cc = s >> 7, ll = s & 127;
                kh[cc*KSTR + ll] = __uint_as_float(Khb[(size_t)(c0+cc)*6400 + l0 + ll]);
                kl[cc*KSTR + ll] = __uint_as_float(Klb[(size_t)(c0+cc)*6400 + l0 + ll]);
            }
            __syncthreads();

            #pragma unroll
            for (int kf = 0; kf < 2; kf++){
                int cr0 = kf*8 + q;
                int cr1 = kf*8 + q + 4;
                uint32_t ah[2][4], al[2][4];
                #pragma unroll
                for (int mf = 0; mf < 2; mf++){
                    int kr = kw*32 + mf*16;
                    ah[mf][0] = __float_as_uint(kh[cr0*KSTR + kr + g    ]);
                    ah[mf][1] = __float_as_uint(kh[cr0*KSTR + kr + g + 8]);
                    ah[mf][2] = __float_as_uint(kh[cr1*KSTR + kr + g    ]);
                    ah[mf][3] = __float_as_uint(kh[cr1*KSTR + kr + g + 8]);
                    al[mf][0] = __float_as_uint(kl[cr0*KSTR + kr + g    ]);
                    al[mf][1] = __float_as_uint(kl[cr0*KSTR + kr + g + 8]);
                    al[mf][2] = __float_as_uint(kl[cr1*KSTR + kr + g    ]);
                    al[mf][3] = __float_as_uint(kl[cr1*KSTR + kr + g + 8]);
                }
                #pragma unroll
                for (int nf = 0; nf < 4; nf++){
                    int col = qw*32 + nf*8 + g;
                    uint32_t bh0 = __float_as_uint(qh[(c0+cr0)*QSTR + col]);
                    uint32_t bh1 = __float_as_uint(qh[(c0+cr1)*QSTR + col]);
                    uint32_t bl0 = __float_as_uint(ql[(c0+cr0)*QSTR + col]);
                    uint32_t bl1 = __float_as_uint(ql[(c0+cr1)*QSTR + col]);
                    #pragma unroll
                    for (int mf = 0; mf < 2; mf++){
                        mma_tf32(acc[mf][nf], al[mf][0],al[mf][1],al[mf][2],al[mf][3], bh0,bh1);
                        mma_tf32(acc[mf][nf], ah[mf][0],ah[mf][1],ah[mf][2],ah[mf][3], bl0,bl1);
                        mma_tf32(acc[mf][nf], ah[mf][0],ah[mf][1],ah[mf][2],ah[mf][3], bh0,bh1);
                    }
                }
            }
        }

        #pragma unroll
        for (int mf = 0; mf < 2; mf++){
            int keyA = l0 + kw*32 + mf*16 + g;
            int keyB = keyA + 8;
            #pragma unroll
            for (int nf = 0; nf < 4; nf++){
                #pragma unroll
                for (int p = 0; p < 2; p++){
                    int sl = nf*2 + p;
                    float vA = acc[mf][nf][p];
                    float vB = acc[mf][nf][2+p];
                    if (vA > bestv[sl]){ bestv[sl] = vA; besti[sl] = keyA; }
                    if (vB > bestv[sl]){ bestv[sl] = vB; besti[sl] = keyB; }
                }
            }
        }
    }

    __syncthreads();
    float* sv = kh;
    float* si = kl;
    #pragma unroll
    for (int nf = 0; nf < 4; nf++)
        #pragma unroll
        for (int p = 0; p < 2; p++){
            int qcol = qw*32 + nf*8 + 2*q + p;
            int sl   = nf*2 + p;
            sv[qcol*32 + kw*8 + g] = bestv[sl];
            si[qcol*32 + kw*8 + g] = __int_as_float(besti[sl]);
        }
    __syncthreads();
    if (tid < 64){
        float bv = -FLT_MAX; int bi = 0x7fffffff;
        for (int t2 = 0; t2 < 32; t2++){
            float v  = sv[tid*32 + t2];
            int   ix = __float_as_int(si[tid*32 + t2]);
            if (v > bv || (v == bv && ix < bi)){ bv = v; bi = ix; }
        }
        int m = m0 + tid;
        mv[((size_t)half*BA + b)*6400 + m] = bv;
        mi[((size_t)half*BA + b)*6400 + m] = bi;
    }
}

// ---------------- merge two k-halves; half1 wins only on strict > ----------------
__global__ void merge_kernel(const float* __restrict__ mv, const int* __restrict__ mi,
                             float* __restrict__ outp){
    int t = blockIdx.x*blockDim.x + threadIdx.x;
    if (t >= BA*6400) return;
    float v0 = mv[t], v1 = mv[BA*6400 + t];
    int   i0 = mi[t], i1 = mi[BA*6400 + t];
    float v = v0; int i = i0;
    if (v1 > v0){ v = v1; i = i1; }
    outp[t]             = v;
    outp[BA*6400 + t]   = (float)i;
}

extern "C" void kernel_launch(void* const* d_in, const int* in_sizes, int n_in,
                              void* d_out, int out_size){
    (void)in_sizes; (void)n_in; (void)out_size;
    const float* query = (const float*)d_in[0];
    const float* key   = (const float*)d_in[1];
    const float* w1 = (const float*)d_in[2];  const float* b1 = (const float*)d_in[3];
    const float* w2 = (const float*)d_in[4];  const float* b2 = (const float*)d_in[5];
    const float* w3 = (const float*)d_in[6];  const float* b3 = (const float*)d_in[7];
    const float* w4 = (const float*)d_in[8];  const float* b4 = (const float*)d_in[9];
    const float* wm = (const float*)d_in[10]; const float* bm = (const float*)d_in[11];
    float* out = (float*)d_out;

    float *up, *bufA, *bufB, *feat, *P, *wT, *mv;
    uint32_t *Ph, *Pl;
    int *mi;
    cudaGetSymbolAddress((void**)&up,     g_up);
    cudaGetSymbolAddress((void**)&bufA,   g_bufA);
    cudaGetSymbolAddress((void**)&bufB,   g_bufB);
    cudaGetSymbolAddress((void**)&feat,   g_feat);
    cudaGetSymbolAddress((void**)&P,      g_P);
    cudaGetSymbolAddress((void**)&Ph,     g_Ph);
    cudaGetSymbolAddress((void**)&Pl,     g_Pl);
    cudaGetSymbolAddress((void**)&wT,     g_wT);
    cudaGetSymbolAddress((void**)&mv,     g_mv);
    cudaGetSymbolAddress((void**)&mi,     g_mi);

    transw_all_kernel<<<(259776+255)/256,256>>>(w1, w2, w3, w4, wT);
    upsample_both_kernel<<<(2*BA*3*320*320+255)/256,256>>>(query, key, up);

    conv3x3_kernel<<<dim3(5,160,4*1),256>>>(up,   wT+OFF_W1, b1, bufA, 3,  64, 320, 320);
    // conv2 tf32 remains overall launch #6 = ncu capture slot
    conv3x3_tf32_kernel<<<dim3(4,320,4*1),256>>>(bufA, wT+OFF_W2, b2, bufB, 64, 64, 320, 320);
    maxpool2_kernel<<<(4*64*160*160+255)/256,256>>>(bufB, bufA, 4*64*160*160, 160, 160);
    conv3x3_tf32_kernel<<<dim3(2,160,4*2),256>>>(bufA, wT+OFF_W3, b3, bufB, 64, 128, 160, 160);
    conv3x3_tf32_kernel<<<dim3(2,160,4*2),256>>>(bufB, wT+OFF_W4, b4, bufA, 128,128, 160, 160);
    maxpool2_kernel<<<(4*128*80*80+255)/256,256>>>(bufA, bufB, 4*128*80*80, 80, 80);
    conv1x1_leaky_kernel<<<(4*16*6400+255)/256,256>>>(bufB, wm, bm, feat);

    patches_norm_kernel<<<(4*6400+255)/256,256>>>(feat, P);
    psplit_kernel<<<(4*144*6400+255)/256,256>>>(P, Ph, Pl);

    size_t match_smem = (2*144*QSTR + 2*16*KSTR) * sizeof(float);   // ~95 KB
    cudaFuncSetAttribute(match_tf32_kernel,
                         cudaFuncAttributeMaxDynamicSharedMemorySize, (int)match_smem);
    match_tf32_kernel<<<dim3(100,BA,2),256,match_smem>>>(Ph, Pl, mv, mi);
    merge_kernel<<<(BA*6400+255)/256,256>>>(mv, mi, out);
}

// round 14
// speedup vs baseline: 1.1082x; 1.1082x over previous
#include <cuda_runtime.h>
#include <cstdint>
#include <cfloat>
#include <math.h>

#define BA 2
#define A_COEF (-0.75f)

__constant__ float c_mean[3] = {0.485f, 0.456f, 0.406f};
__constant__ float c_std[3]  = {0.229f, 0.224f, 0.225f};

// ---------------- scratch (static device memory) ----------------
__device__ float    g_up   [4*3*320*320];
__device__ float    g_bufA [4*64*320*320];
__device__ float    g_bufB [4*64*320*320];
__device__ float    g_feat [4*16*80*80];
__device__ float    g_P    [4*144*6400];
__device__ uint32_t g_Ph   [4*144*6400];
__device__ uint32_t g_Pl   [4*144*6400];
__device__ float    g_wT   [259776];
__device__ float    g_mv   [2*BA*6400];
__device__ int      g_mi   [2*BA*6400];

#define OFF_W1 0
#define OFF_W2 1728
#define OFF_W3 38592
#define OFF_W4 112320

__device__ __forceinline__ float cubicw(float d){
    d = fabsf(d);
    if (d <= 1.f) return ((A_COEF + 2.f)*d - (A_COEF + 3.f))*d*d + 1.f;
    if (d < 2.f)  return A_COEF*(((d - 5.f)*d + 8.f)*d - 4.f);
    return 0.f;
}

// ---------------- tf32 helpers ----------------
__device__ __forceinline__ void split_tf32(float x, uint32_t& hi, uint32_t& lo){
    uint32_t h;
    asm("cvt.rna.tf32.f32 %0, %1;" : "=r"(h) : "f"(x));
    float l = x - __uint_as_float(h);
    uint32_t lr;
    asm("cvt.rna.tf32.f32 %0, %1;" : "=r"(lr) : "f"(l));
    hi = h; lo = lr;
}

__device__ __forceinline__ void mma_tf32(float* c,
        uint32_t a0, uint32_t a1, uint32_t a2, uint32_t a3,
        uint32_t b0, uint32_t b1){
    asm volatile("mma.sync.aligned.m16n8k8.row.col.f32.tf32.tf32.f32 "
        "{%0,%1,%2,%3}, {%4,%5,%6,%7}, {%8,%9}, {%0,%1,%2,%3};"
        : "+f"(c[0]),"+f"(c[1]),"+f"(c[2]),"+f"(c[3])
        : "r"(a0),"r"(a1),"r"(a2),"r"(a3), "r"(b0),"r"(b1));
}

// ---------------- cp.async helpers ----------------
__device__ __forceinline__ uint32_t smem_u32(const void* p){
    return (uint32_t)__cvta_generic_to_shared(p);
}
__device__ __forceinline__ void cp_async4(uint32_t saddr, const void* gptr, bool pred){
    int sz = pred ? 4 : 0;
    asm volatile("cp.async.ca.shared.global [%0], [%1], 4, %2;\n"
        :: "r"(saddr), "l"(gptr), "r"(sz));
}
#define CP_COMMIT()  asm volatile("cp.async.commit_group;\n" ::)
#define CP_WAIT0()   asm volatile("cp.async.wait_group 0;\n" ::)

// ---------------- merged weight transpose ----------------
__global__ void transw_all_kernel(const float* __restrict__ w1, const float* __restrict__ w2,
                                  const float* __restrict__ w3, const float* __restrict__ w4,
                                  float* __restrict__ wT){
    int t = blockIdx.x*blockDim.x + threadIdx.x;
    if (t >= 259776) return;
    const float* w; int CO, CI, base;
    if (t < 38592){
        if (t < 1728){ w = w1; CO = 64;  CI = 3;   base = OFF_W1; }
        else         { w = w2; CO = 64;  CI = 64;  base = OFF_W2; }
    } else {
        if (t < 112320){ w = w3; CO = 128; CI = 64;  base = OFF_W3; }
        else           { w = w4; CO = 128; CI = 128; base = OFF_W4; }
    }
    int loc = t - base;
    int co  = loc / (CI*9);
    int r   = loc - co*(CI*9);
    wT[base + r*CO + co] = w[loc];
}

// ---------------- P tf32 pre-split ----------------
__global__ void psplit_kernel(const float* __restrict__ P, uint32_t* __restrict__ Ph,
                              uint32_t* __restrict__ Pl){
    int t = blockIdx.x*blockDim.x + threadIdx.x;
    if (t >= 4*144*6400) return;
    uint32_t h, l;
    split_tf32(P[t], h, l);
    Ph[t] = h; Pl[t] = l;
}

// ---------------- maxpool 2x2 stride 2 ----------------
__global__ void maxpool2_kernel(const float* __restrict__ in, float* __restrict__ out,
                                int total, int H2, int W2){
    int t = blockIdx.x*blockDim.x + threadIdx.x;
    if (t >= total) return;
    int x  = t % W2;
    int y  = (t / W2) % H2;
    int bc = t / (W2*H2);
    const float* p = in + (((size_t)bc*(H2*2)) + y*2)*(W2*2) + x*2;
    out[t] = fmaxf(fmaxf(p[0], p[1]), fmaxf(p[W2*2], p[W2*2+1]));
}

// ---------------- merged: sub_mean + bicubic upsample x2 for BOTH paths ----------------
__global__ void upsample_both_kernel(const float* __restrict__ query,
                                     const float* __restrict__ key,
                                     float* __restrict__ dst){
    const int HALF = BA*3*320*320;
    int t = blockIdx.x*blockDim.x + threadIdx.x;
    if (t >= 2*HALF) return;
    int path = t / HALF;
    int r    = t - path*HALF;
    int ox = r % 320;
    int oy = (r / 320) % 320;
    int c  = (r / (320*320)) % 3;
    int b  = r / (320*320*3);

    const int Hs = 160, Ws = 160;
    float sy = (float)((double)(Hs-1) / 319.0);
    float sx = (float)((double)(Ws-1) / 319.0);
    float cy = (float)oy * sy;
    float cx = (float)ox * sx;
    float fy = floorf(cy), fx = floorf(cx);
    float tv = cy - fy,    tu = cx - fx;
    int iy = (int)fy, ix = (int)fx;

    float wy[4] = {cubicw(tv+1.f), cubicw(tv), cubicw(tv-1.f), cubicw(tv-2.f)};
    float wx[4] = {cubicw(tu+1.f), cubicw(tu), cubicw(tu-1.f), cubicw(tu-2.f)};

    float mean = c_mean[c], stdv = c_std[c];
    const float* qp = query + ((size_t)b*3 + c)*Hs*Ws;
    const float* kp = key   + ((size_t)b*3 + c)*320*320;

    float acc = 0.f;
    #pragma unroll
    for (int j = 0; j < 4; j++){
        int xx = ix - 1 + j;
        xx = xx < 0 ? 0 : (xx > Ws-1 ? Ws-1 : xx);
        float colsum = 0.f;
        #pragma unroll
        for (int i = 0; i < 4; i++){
            int yy = iy - 1 + i;
            yy = yy < 0 ? 0 : (yy > Hs-1 ? Hs-1 : yy);
            float s;
            if (path == 0){
                s = qp[yy*Ws + xx];
            } else {
                const float* p = kp + (yy*2)*320 + xx*2;
                s = (p[0] + p[1] + p[320] + p[321]) / 4.0f;
            }
            float v = (s - mean) / stdv;
            colsum += wy[i]*v;
        }
        acc += wx[j]*colsum;
    }
    dst[(size_t)path*HALF + r] = acc;
}

// ---------------- conv3x3 FFMA (CI=3 first layer) ----------------
__global__ __launch_bounds__(256)
void conv3x3_kernel(const float* __restrict__ in, const float* __restrict__ wT,
                    const float* __restrict__ bias, float* __restrict__ out,
                    int CI, int CO, int H, int W){
    __shared__ float insm[8*4*72];
    __shared__ float wsm [72*64];

    int tid = threadIdx.x;
    int tx = tid & 15;
    int ty = tid >> 4;
    int x0 = blockIdx.x * 64;
    int y0 = blockIdx.y * 2;
    int cog = CO >> 6;
    int b   = blockIdx.z / cog;
    int co0 = (blockIdx.z % cog) << 6;

    float acc[4][2][4];
    #pragma unroll
    for (int i = 0; i < 4; i++)
        #pragma unroll
        for (int r = 0; r < 2; r++)
            #pragma unroll
            for (int j = 0; j < 4; j++) acc[i][r][j] = 0.f;

    const float* inb = in + (size_t)b*CI*H*W;

    for (int ci0 = 0; ci0 < CI; ci0 += 8){
        int cn = CI - ci0; if (cn > 8) cn = 8;
        __syncthreads();
        int nin = cn*264;
        for (int s = tid; s < nin; s += 256){
            int ci  = s / 264;
            int rem = s - ci*264;
            int r   = rem / 66;
            int xx  = rem - r*66;
            int gy = y0 + r - 1;
            int gx = x0 + xx - 1;
            float v = 0.f;
            if (gy >= 0 && gy < H && gx >= 0 && gx < W)
                v = inb[((size_t)(ci0+ci)*H + gy)*W + gx];
            insm[(ci*4 + r)*72 + xx] = v;
        }
        int kk = cn*9;
        for (int s = tid; s < kk*64; s += 256){
            int k  = s >> 6;
            int co = s & 63;
            wsm[k*64 + co] = wT[((size_t)ci0*9 + k)*CO + co0 + co];
        }
        __syncthreads();

        float accc[4][2][4];
        #pragma unroll
        for (int i = 0; i < 4; i++)
            #pragma unroll
            for (int r = 0; r < 2; r++)
                #pragma unroll
                for (int j = 0; j < 4; j++) accc[i][r][j] = 0.f;

        for (int ci = 0; ci < cn; ci++){
            #pragma unroll
            for (int dy = 0; dy < 3; dy++){
                const float* ipa = &insm[(ci*4 + dy)*72 + tx*4];
                float a6[6], b6[6];
                #pragma unroll
                for (int u = 0; u < 6; u++){ a6[u] = ipa[u]; b6[u] = ipa[72+u]; }
                #pragma unroll
                for (int dx = 0; dx < 3; dx++){
                    float4 wv = *(const float4*)&wsm[(ci*9 + dy*3 + dx)*64 + ty*4];
                    #pragma unroll
                    for (int j = 0; j < 4; j++){
                        float ia = a6[dx + j];
                        float ib = b6[dx + j];
                        accc[0][0][j] += wv.x * ia;  accc[0][1][j] += wv.x * ib;
                        accc[1][0][j] += wv.y * ia;  accc[1][1][j] += wv.y * ib;
                        accc[2][0][j] += wv.z * ia;  accc[2][1][j] += wv.z * ib;
                        accc[3][0][j] += wv.w * ia;  accc[3][1][j] += wv.w * ib;
                    }
                }
            }
        }
        #pragma unroll
        for (int i = 0; i < 4; i++)
            #pragma unroll
            for (int r = 0; r < 2; r++)
                #pragma unroll
                for (int j = 0; j < 4; j++) acc[i][r][j] += accc[i][r][j];
    }

    #pragma unroll
    for (int i = 0; i < 4; i++){
        int co = co0 + ty*4 + i;
        float bv = bias[co];
        #pragma unroll
        for (int r = 0; r < 2; r++){
            #pragma unroll
            for (int j = 0; j < 4; j++){
                int x = x0 + tx*4 + j;
                if (x < W){
                    float v = acc[i][r][j] + bv;
                    out[(((size_t)b*CO + co)*H + (y0+r))*W + x] = fmaxf(v, 0.f);
                }
            }
        }
    }
}

// ---------------- conv3x3 3xTF32, 2 rows/block, cp.async double-buffered (race-fixed) ----------------
// Order per iteration: wait chunk c -> barrier -> split -> barrier -> issue chunk c+1
// -> compute. Every buffer write is now two barriers after its last reader.
#define ISM_N   (8*4*84)
#define STG_N   (8*4*82)
#define WSM_N   (9*8*65)
#define CONV_SMEM_FLOATS (2*ISM_N + 2*STG_N + 2*WSM_N)

__global__ __launch_bounds__(256)
void conv3x3_tf32_kernel(const float* __restrict__ in, const float* __restrict__ wT,
                         const float* __restrict__ bias, float* __restrict__ out,
                         int CI, int CO, int H, int W){
    extern __shared__ float csm[];
    float* ismh = csm;
    float* isml = ismh + ISM_N;
    float* stg  = isml + ISM_N;          // [2][STG_N]
    float* wsm  = stg + 2*STG_N;         // [2][WSM_N]

    int tid  = threadIdx.x;
    int warp = tid >> 5, lane = tid & 31;
    int wm = warp & 3;
    int wn = warp >> 2;
    int g  = lane >> 2;
    int q  = lane & 3;

    int x0 = blockIdx.x * 80;
    int y0 = blockIdx.y * 2;
    int cog = CO >> 6;
    int b   = blockIdx.z / cog;
    int co0 = (blockIdx.z % cog) << 6;

    const float* inb = in + (size_t)b*CI*H*W;
    uint32_t stg_base = smem_u32(stg);
    uint32_t wsm_base = smem_u32(wsm);

    float cacc[2][5][4];
    #pragma unroll
    for (int r = 0; r < 2; r++)
        #pragma unroll
        for (int nt = 0; nt < 5; nt++)
            #pragma unroll
            for (int i = 0; i < 4; i++) cacc[r][nt][i] = 0.f;

    int nch = CI >> 3;

    auto issue_chunk = [&](int ci0, int buf){
        for (int s = tid; s < STG_N; s += 256){
            int ci  = s / 328;
            int rem = s - ci*328;
            int r   = rem / 82;
            int col = rem - r*82;
            int gy = y0 + r - 1;
            int gx = x0 + col - 1;
            bool ok = (gy >= 0 && gy < H && gx >= 0 && gx < W);
            const float* gp = ok ? (inb + ((size_t)(ci0+ci)*H + gy)*W + gx) : inb;
            cp_async4(stg_base + (uint32_t)(buf*STG_N + s)*4u, gp, ok);
        }
        for (int s = tid; s < 9*8*64; s += 256){
            int tap = s >> 9;
            int rem = s & 511;
            int ci  = rem >> 6;
            int co  = rem & 63;
            cp_async4(wsm_base + (uint32_t)(buf*WSM_N + (tap*8+ci)*65 + co)*4u,
                      wT + ((size_t)(ci0+ci)*9 + tap)*CO + co0 + co, true);
        }
        CP_COMMIT();
    };

    issue_chunk(0, 0);

    for (int c = 0; c < nch; c++){
        int buf = c & 1;
        CP_WAIT0();          // chunk c (and anything earlier) fully landed
        __syncthreads();     // ALL threads done with previous compute AND see chunk c

        // split stage -> hi/lo (same values/layout as the bit-exact R11 kernel)
        const float* sb = stg + buf*STG_N;
        for (int s = tid; s < STG_N; s += 256){
            int ci  = s / 328;
            int rem = s - ci*328;
            int r   = rem / 82;
            int col = rem - r*82;
            uint32_t h, l;
            split_tf32(sb[s], h, l);
            ismh[(ci*4 + r)*84 + col] = __uint_as_float(h);
            isml[(ci*4 + r)*84 + col] = __uint_as_float(l);
        }
        __syncthreads();     // split visible; everyone past reading stg[buf^1]/wsm[buf^1]

        if (c + 1 < nch) issue_chunk((c+1)*8, buf^1);   // overlaps with compute below

        const float* wp = wsm + buf*WSM_N;
        #pragma unroll
        for (int dy = 0; dy < 3; dy++){
            #pragma unroll
            for (int dx = 0; dx < 3; dx++){
                int tap = dy*3 + dx;
                float a0 = wp[(tap*8 + q  )*65 + wm*16 + g    ];
                float a1 = wp[(tap*8 + q  )*65 + wm*16 + g + 8];
                float a2 = wp[(tap*8 + q+4)*65 + wm*16 + g    ];
                float a3 = wp[(tap*8 + q+4)*65 + wm*16 + g + 8];
                uint32_t ah0,al0,ah1,al1,ah2,al2,ah3,al3;
                split_tf32(a0, ah0, al0);
                split_tf32(a1, ah1, al1);
                split_tf32(a2, ah2, al2);
                split_tf32(a3, ah3, al3);
                #pragma unroll
                for (int r = 0; r < 2; r++){
                    #pragma unroll
                    for (int nt = 0; nt < 5; nt++){
                        int col = wn*40 + nt*8 + g + dx;
                        int i0 = ( q   *4 + r + dy)*84 + col;
                        int i1 = ((q+4)*4 + r + dy)*84 + col;
                        uint32_t bh0 = __float_as_uint(ismh[i0]);
                        uint32_t bh1 = __float_as_uint(ismh[i1]);
                        uint32_t bl0 = __float_as_uint(isml[i0]);
                        uint32_t bl1 = __float_as_uint(isml[i1]);
                        mma_tf32(cacc[r][nt], al0,al1,al2,al3, bh0,bh1);
                        mma_tf32(cacc[r][nt], ah0,ah1,ah2,ah3, bl0,bl1);
                        mma_tf32(cacc[r][nt], ah0,ah1,ah2,ah3, bh0,bh1);
                    }
                }
            }
        }
    }

    int coA = co0 + wm*16 + g;
    int coB = coA + 8;
    float bvA = bias[coA], bvB = bias[coB];
    #pragma unroll
    for (int r = 0; r < 2; r++){
        float* outA = out + (((size_t)b*CO + coA)*H + (y0+r))*W;
        float* outB = out + (((size_t)b*CO + coB)*H + (y0+r))*W;
        #pragma unroll
        for (int nt = 0; nt < 5; nt++){
            int x = x0 + wn*40 + nt*8 + 2*q;
            outA[x  ] = fmaxf(cacc[r][nt][0] + bvA, 0.f);
            outA[x+1] = fmaxf(cacc[r][nt][1] + bvA, 0.f);
            outB[x  ] = fmaxf(cacc[r][nt][2] + bvB, 0.f);
            outB[x+1] = fmaxf(cacc[r][nt][3] + bvB, 0.f);
        }
    }
}

// ---------------- 1x1 map conv (128 -> 16) + LeakyReLU(0.2), B=4 ----------------
__global__ void conv1x1_leaky_kernel(const float* __restrict__ in, const float* __restrict__ w,
                                     const float* __restrict__ bias, float* __restrict__ out){
    int t = blockIdx.x*blockDim.x + threadIdx.x;
    if (t >= 4*16*6400) return;
    int px = t % 6400;
    int co = (t / 6400) % 16;
    int b  = t / (6400*16);
    const float* ip = in + (size_t)b*128*6400 + px;
    const float* wp = w + co*128;
    float s = 0.f;
    for (int c0 = 0; c0 < 128; c0 += 16){
        float sc = 0.f;
        #pragma unroll
        for (int ci = 0; ci < 16; ci++) sc += ip[(size_t)(c0+ci)*6400] * wp[c0+ci];
        s += sc;
    }
    s += bias[co];
    out[t] = s > 0.f ? s : 0.2f*s;
}

// ---------------- 3x3 unfold (reflect pad) + per-position L2 normalize, B=4 ----------------
__global__ void patches_norm_kernel(const float* __restrict__ f, float* __restrict__ P){
    int t = blockIdx.x*blockDim.x + threadIdx.x;
    if (t >= 4*6400) return;
    int m = t % 6400;
    int b = t / 6400;
    int y = m / 80, x = m % 80;
    int ry[3], rx[3];
    #pragma unroll
    for (int i = 0; i < 3; i++){
        int yy = y + i - 1; ry[i] = yy < 0 ? -yy : (yy > 79 ? 158 - yy : yy);
        int xx = x + i - 1; rx[i] = xx < 0 ? -xx : (xx > 79 ? 158 - xx : xx);
    }
    const float* fb = f + (size_t)b*16*6400;
    float ss = 0.f;
    for (int c = 0; c < 16; c++){
        const float* fc = fb + c*6400;
        float sc = 0.f;
        #pragma unroll
        for (int i = 0; i < 3; i++)
            #pragma unroll
            for (int j = 0; j < 3; j++){
                float v = fc[ry[i]*80 + rx[j]];
                sc += v*v;
            }
        ss += sc;
    }
    float nrm = fmaxf(sqrtf(ss), 1e-12f);
    float* Pb = P + (size_t)b*144*6400;
    for (int c = 0; c < 16; c++){
        const float* fc = fb + c*6400;
        #pragma unroll
        for (int i = 0; i < 3; i++)
            #pragma unroll
            for (int j = 0; j < 3; j++)
                Pb[(size_t)(c*9 + i*3 + j)*6400 + m] = fc[ry[i]*80 + rx[j]] / nrm;
    }
}

// ---------------- cosine-sim via 3xTF32 mma v2 + streaming max/argmax ----------------
#define QSTR 68
#define KSTR 132
__global__ __launch_bounds__(256)
void match_tf32_kernel(const uint32_t* __restrict__ Ph, const uint32_t* __restrict__ Pl,
                       float* __restrict__ mv, int* __restrict__ mi){
    extern __shared__ float dsm[];
    float* qh = dsm;
    float* ql = qh + 144*QSTR;
    float* kh = ql + 144*QSTR;
    float* kl = kh + 16*KSTR;

    int b    = blockIdx.y;
    int half = blockIdx.z;
    int m0   = blockIdx.x * 64;
    int tid  = threadIdx.x;
    int warp = tid >> 5, lane = tid & 31;
    int kw = warp & 3;
    int qw = warp >> 2;
    int g  = lane >> 2;
    int q  = lane & 3;

    const uint32_t* Qhb = Ph + (size_t)b*144*6400;
    const uint32_t* Qlb = Pl + (size_t)b*144*6400;
    const uint32_t* Khb = Ph + (size_t)(2+b)*144*6400;
    const uint32_t* Klb = Pl + (size_t)(2+b)*144*6400;

    for (int s = tid; s < 144*64; s += 256){
        int c = s >> 6, mm = s & 63;
        qh[c*QSTR + mm] = __uint_as_float(Qhb[(size_t)c*6400 + m0 + mm]);
        ql[c*QSTR + mm] = __uint_as_float(Qlb[(size_t)c*6400 + m0 + mm]);
    }

    float bestv[8];
    int   besti[8];
    #pragma unroll
    for (int i = 0; i < 8; i++){ bestv[i] = -FLT_MAX; besti[i] = 0; }

    int lbeg = half*3200, lend = lbeg + 3200;
    for (int l0 = lbeg; l0 < lend; l0 += 128){
        float acc[2][4][4];
        #pragma unroll
        for (int mf = 0; mf < 2; mf++)
            #pragma unroll
            for (int nf = 0; nf < 4; nf++)
                #pragma unroll
                for (int i = 0; i < 4; i++) acc[mf][nf][i] = 0.f;

        for (int c0 = 0; c0 < 144; c0 += 16){
            __syncthreads();
            for (int s = tid; s < 16*128; s += 256){
                int cc = s >> 7, ll = s & 127;
                kh[cc*KSTR + ll] = __uint_as_float(Khb[(size_t)(c0+cc)*6400 + l0 + ll]);
                kl[cc*KSTR + ll] = __uint_as_float(Klb[(size_t)(c0+cc)*6400 + l0 + ll]);
            }
            __syncthreads();

            #pragma unroll
            for (int kf = 0; kf < 2; kf++){
                int cr0 = kf*8 + q;
                int cr1 = kf*8 + q + 4;
                uint32_t ah[2][4], al[2][4];
                #pragma unroll
                for (int mf = 0; mf < 2; mf++){
                    int kr = kw*32 + mf*16;
                    ah[mf][0] = __float_as_uint(kh[cr0*KSTR + kr + g    ]);
                    ah[mf][1] = __float_as_uint(kh[cr0*KSTR + kr + g + 8]);
                    ah[mf][2] = __float_as_uint(kh[cr1*KSTR + kr + g    ]);
                    ah[mf][3] = __float_as_uint(kh[cr1*KSTR + kr + g + 8]);
                    al[mf][0] = __float_as_uint(kl[cr0*KSTR + kr + g    ]);
                    al[mf][1] = __float_as_uint(kl[cr0*KSTR + kr + g + 8]);
                    al[mf][2] = __float_as_uint(kl[cr1*KSTR + kr + g    ]);
                    al[mf][3] = __float_as_uint(kl[cr1*KSTR + kr + g + 8]);
                }
                #pragma unroll
                for (int nf = 0; nf < 4; nf++){
                    int col = qw*32 + nf*8 + g;
                    uint32_t bh0 = __float_as_uint(qh[(c0+cr0)*QSTR + col]);
                    uint32_t bh1 = __float_as_uint(qh[(c0+cr1)*QSTR + col]);
                    uint32_t bl0 = __float_as_uint(ql[(c0+cr0)*QSTR + col]);
                    uint32_t bl1 = __float_as_uint(ql[(c0+cr1)*QSTR + col]);
                    #pragma unroll
                    for (int mf = 0; mf < 2; mf++){
                        mma_tf32(acc[mf][nf], al[mf][0],al[mf][1],al[mf][2],al[mf][3], bh0,bh1);
                        mma_tf32(acc[mf][nf], ah[mf][0],ah[mf][1],ah[mf][2],ah[mf][3], bl0,bl1);
                        mma_tf32(acc[mf][nf], ah[mf][0],ah[mf][1],ah[mf][2],ah[mf][3], bh0,bh1);
                    }
                }
            }
        }

        #pragma unroll
        for (int mf = 0; mf < 2; mf++){
            int keyA = l0 + kw*32 + mf*16 + g;
            int keyB = keyA + 8;
            #pragma unroll
            for (int nf = 0; nf < 4; nf++){
                #pragma unroll
                for (int p = 0; p < 2; p++){
                    int sl = nf*2 + p;
                    float vA = acc[mf][nf][p];
                    float vB = acc[mf][nf][2+p];
                    if (vA > bestv[sl]){ bestv[sl] = vA; besti[sl] = keyA; }
                    if (vB > bestv[sl]){ bestv[sl] = vB; besti[sl] = keyB; }
                }
            }
        }
    }

    __syncthreads();
    float* sv = kh;
    float* si = kl;
    #pragma unroll
    for (int nf = 0; nf < 4; nf++)
        #pragma unroll
        for (int p = 0; p < 2; p++){
            int qcol = qw*32 + nf*8 + 2*q + p;
            int sl   = nf*2 + p;
            sv[qcol*32 + kw*8 + g] = bestv[sl];
            si[qcol*32 + kw*8 + g] = __int_as_float(besti[sl]);
        }
    __syncthreads();
    if (tid < 64){
        float bv = -FLT_MAX; int bi = 0x7fffffff;
        for (int t2 = 0; t2 < 32; t2++){
            float v  = sv[tid*32 + t2];
            int   ix = __float_as_int(si[tid*32 + t2]);
            if (v > bv || (v == bv && ix < bi)){ bv = v; bi = ix; }
        }
        int m = m0 + tid;
        mv[((size_t)half*BA + b)*6400 + m] = bv;
        mi[((size_t)half*BA + b)*6400 + m] = bi;
    }
}

// ---------------- merge two k-halves ----------------
__global__ void merge_kernel(const float* __restrict__ mv, const int* __restrict__ mi,
                             float* __restrict__ outp){
    int t = blockIdx.x*blockDim.x + threadIdx.x;
    if (t >= BA*6400) return;
    float v0 = mv[t], v1 = mv[BA*6400 + t];
    int   i0 = mi[t], i1 = mi[BA*6400 + t];
    float v = v0; int i = i0;
    if (v1 > v0){ v = v1; i = i1; }
    outp[t]             = v;
    outp[BA*6400 + t]   = (float)i;
}

extern "C" void kernel_launch(void* const* d_in, const int* in_sizes, int n_in,
                              void* d_out, int out_size){
    (void)in_sizes; (void)n_in; (void)out_size;
    const float* query = (const float*)d_in[0];
    const float* key   = (const float*)d_in[1];
    const float* w1 = (const float*)d_in[2];  const float* b1 = (const float*)d_in[3];
    const float* w2 = (const float*)d_in[4];  const float* b2 = (const float*)d_in[5];
    const float* w3 = (const float*)d_in[6];  const float* b3 = (const float*)d_in[7];
    const float* w4 = (const float*)d_in[8];  const float* b4 = (const float*)d_in[9];
    const float* wm = (const float*)d_in[10]; const float* bm = (const float*)d_in[11];
    float* out = (float*)d_out;

    float *up, *bufA, *bufB, *feat, *P, *wT, *mv;
    uint32_t *Ph, *Pl;
    int *mi;
    cudaGetSymbolAddress((void**)&up,     g_up);
    cudaGetSymbolAddress((void**)&bufA,   g_bufA);
    cudaGetSymbolAddress((void**)&bufB,   g_bufB);
    cudaGetSymbolAddress((void**)&feat,   g_feat);
    cudaGetSymbolAddress((void**)&P,      g_P);
    cudaGetSymbolAddress((void**)&Ph,     g_Ph);
    cudaGetSymbolAddress((void**)&Pl,     g_Pl);
    cudaGetSymbolAddress((void**)&wT,     g_wT);
    cudaGetSymbolAddress((void**)&mv,     g_mv);
    cudaGetSymbolAddress((void**)&mi,     g_mi);

    size_t conv_smem = CONV_SMEM_FLOATS * sizeof(float);   // ~80 KB
    cudaFuncSetAttribute(conv3x3_tf32_kernel,
                         cudaFuncAttributeMaxDynamicSharedMemorySize, (int)conv_smem);

    transw_all_kernel<<<(259776+255)/256,256>>>(w1, w2, w3, w4, wT);
    upsample_both_kernel<<<(2*BA*3*320*320+255)/256,256>>>(query, key, up);

    conv3x3_kernel<<<dim3(5,160,4*1),256>>>(up,   wT+OFF_W1, b1, bufA, 3,  64, 320, 320);
    // conv2 tf32 remains overall launch #6 = ncu capture slot
    conv3x3_tf32_kernel<<<dim3(4,160,4*1),256,conv_smem>>>(bufA, wT+OFF_W2, b2, bufB, 64, 64, 320, 320);
    maxpool2_kernel<<<(4*64*160*160+255)/256,256>>>(bufB, bufA, 4*64*160*160, 160, 160);
    conv3x3_tf32_kernel<<<dim3(2,80,4*2),256,conv_smem>>>(bufA, wT+OFF_W3, b3, bufB, 64, 128, 160, 160);
    conv3x3_tf32_kernel<<<dim3(2,80,4*2),256,conv_smem>>>(bufB, wT+OFF_W4, b4, bufA, 128,128, 160, 160);
    maxpool2_kernel<<<(4*128*80*80+255)/256,256>>>(bufA, bufB, 4*128*80*80, 80, 80);
    conv1x1_leaky_kernel<<<(4*16*6400+255)/256,256>>>(bufB, wm, bm, feat);

    patches_norm_kernel<<<(4*6400+255)/256,256>>>(feat, P);
    psplit_kernel<<<(4*144*6400+255)/256,256>>>(P, Ph, Pl);

    size_t match_smem = (2*144*QSTR + 2*16*KSTR) * sizeof(float);   // ~95 KB
    cudaFuncSetAttribute(match_tf32_kernel,
                         cudaFuncAttributeMaxDynamicSharedMemorySize, (int)match_smem);
    match_tf32_kernel<<<dim3(100,BA,2),256,match_smem>>>(Ph, Pl, mv, mi);
    merge_kernel<<<(BA*6400+255)/256,256>>>(mv, mi, out);
}

// round 15
// speedup vs baseline: 1.2527x; 1.1304x over previous
#include <cuda_runtime.h>
#include <cstdint>
#include <cfloat>
#include <math.h>

#define BA 2
#define A_COEF (-0.75f)

__constant__ float c_mean[3] = {0.485f, 0.456f, 0.406f};
__constant__ float c_std[3]  = {0.229f, 0.224f, 0.225f};

// ---------------- scratch (static device memory) ----------------
__device__ float    g_up   [4*3*320*320];
__device__ float    g_bufA [4*64*320*320];
__device__ float    g_bufB [4*64*320*320];
__device__ float    g_feat [4*16*80*80];
__device__ float    g_P    [4*144*6400];
__device__ uint32_t g_Ph   [4*144*6400];
__device__ uint32_t g_Pl   [4*144*6400];
__device__ float    g_wT   [259776];
__device__ float    g_mv   [2*BA*6400];
__device__ int      g_mi   [2*BA*6400];

#define OFF_W1 0
#define OFF_W2 1728
#define OFF_W3 38592
#define OFF_W4 112320

__device__ __forceinline__ float cubicw(float d){
    d = fabsf(d);
    if (d <= 1.f) return ((A_COEF + 2.f)*d - (A_COEF + 3.f))*d*d + 1.f;
    if (d < 2.f)  return A_COEF*(((d - 5.f)*d + 8.f)*d - 4.f);
    return 0.f;
}

// ---------------- tf32 helpers ----------------
__device__ __forceinline__ void split_tf32(float x, uint32_t& hi, uint32_t& lo){
    uint32_t h;
    asm("cvt.rna.tf32.f32 %0, %1;" : "=r"(h) : "f"(x));
    float l = x - __uint_as_float(h);
    uint32_t lr;
    asm("cvt.rna.tf32.f32 %0, %1;" : "=r"(lr) : "f"(l));
    hi = h; lo = lr;
}

__device__ __forceinline__ void mma_tf32(float* c,
        uint32_t a0, uint32_t a1, uint32_t a2, uint32_t a3,
        uint32_t b0, uint32_t b1){
    asm volatile("mma.sync.aligned.m16n8k8.row.col.f32.tf32.tf32.f32 "
        "{%0,%1,%2,%3}, {%4,%5,%6,%7}, {%8,%9}, {%0,%1,%2,%3};"
        : "+f"(c[0]),"+f"(c[1]),"+f"(c[2]),"+f"(c[3])
        : "r"(a0),"r"(a1),"r"(a2),"r"(a3), "r"(b0),"r"(b1));
}

// ---------------- cp.async helpers ----------------
__device__ __forceinline__ uint32_t smem_u32(const void* p){
    return (uint32_t)__cvta_generic_to_shared(p);
}
__device__ __forceinline__ void cp_async4(uint32_t saddr, const void* gptr, bool pred){
    int sz = pred ? 4 : 0;
    asm volatile("cp.async.ca.shared.global [%0], [%1], 4, %2;\n"
        :: "r"(saddr), "l"(gptr), "r"(sz));
}
#define CP_COMMIT()  asm volatile("cp.async.commit_group;\n" ::)
#define CP_WAIT0()   asm volatile("cp.async.wait_group 0;\n" ::)

// ---------------- merged weight transpose ----------------
__global__ void transw_all_kernel(const float* __restrict__ w1, const float* __restrict__ w2,
                                  const float* __restrict__ w3, const float* __restrict__ w4,
                                  float* __restrict__ wT){
    int t = blockIdx.x*blockDim.x + threadIdx.x;
    if (t >= 259776) return;
    const float* w; int CO, CI, base;
    if (t < 38592){
        if (t < 1728){ w = w1; CO = 64;  CI = 3;   base = OFF_W1; }
        else         { w = w2; CO = 64;  CI = 64;  base = OFF_W2; }
    } else {
        if (t < 112320){ w = w3; CO = 128; CI = 64;  base = OFF_W3; }
        else           { w = w4; CO = 128; CI = 128; base = OFF_W4; }
    }
    int loc = t - base;
    int co  = loc / (CI*9);
    int r   = loc - co*(CI*9);
    wT[base + r*CO + co] = w[loc];
}

// ---------------- P tf32 pre-split ----------------
__global__ void psplit_kernel(const float* __restrict__ P, uint32_t* __restrict__ Ph,
                              uint32_t* __restrict__ Pl){
    int t = blockIdx.x*blockDim.x + threadIdx.x;
    if (t >= 4*144*6400) return;
    uint32_t h, l;
    split_tf32(P[t], h, l);
    Ph[t] = h; Pl[t] = l;
}

// ---------------- maxpool 2x2 stride 2 ----------------
__global__ void maxpool2_kernel(const float* __restrict__ in, float* __restrict__ out,
                                int total, int H2, int W2){
    int t = blockIdx.x*blockDim.x + threadIdx.x;
    if (t >= total) return;
    int x  = t % W2;
    int y  = (t / W2) % H2;
    int bc = t / (W2*H2);
    const float* p = in + (((size_t)bc*(H2*2)) + y*2)*(W2*2) + x*2;
    out[t] = fmaxf(fmaxf(p[0], p[1]), fmaxf(p[W2*2], p[W2*2+1]));
}

// ---------------- merged: sub_mean + bicubic upsample x2 for BOTH paths ----------------
__global__ void upsample_both_kernel(const float* __restrict__ query,
                                     const float* __restrict__ key,
                                     float* __restrict__ dst){
    const int HALF = BA*3*320*320;
    int t = blockIdx.x*blockDim.x + threadIdx.x;
    if (t >= 2*HALF) return;
    int path = t / HALF;
    int r    = t - path*HALF;
    int ox = r % 320;
    int oy = (r / 320) % 320;
    int c  = (r / (320*320)) % 3;
    int b  = r / (320*320*3);

    const int Hs = 160, Ws = 160;
    float sy = (float)((double)(Hs-1) / 319.0);
    float sx = (float)((double)(Ws-1) / 319.0);
    float cy = (float)oy * sy;
    float cx = (float)ox * sx;
    float fy = floorf(cy), fx = floorf(cx);
    float tv = cy - fy,    tu = cx - fx;
    int iy = (int)fy, ix = (int)fx;

    float wy[4] = {cubicw(tv+1.f), cubicw(tv), cubicw(tv-1.f), cubicw(tv-2.f)};
    float wx[4] = {cubicw(tu+1.f), cubicw(tu), cubicw(tu-1.f), cubicw(tu-2.f)};

    float mean = c_mean[c], stdv = c_std[c];
    const float* qp = query + ((size_t)b*3 + c)*Hs*Ws;
    const float* kp = key   + ((size_t)b*3 + c)*320*320;

    float acc = 0.f;
    #pragma unroll
    for (int j = 0; j < 4; j++){
        int xx = ix - 1 + j;
        xx = xx < 0 ? 0 : (xx > Ws-1 ? Ws-1 : xx);
        float colsum = 0.f;
        #pragma unroll
        for (int i = 0; i < 4; i++){
            int yy = iy - 1 + i;
            yy = yy < 0 ? 0 : (yy > Hs-1 ? Hs-1 : yy);
            float s;
            if (path == 0){
                s = qp[yy*Ws + xx];
            } else {
                const float* p = kp + (yy*2)*320 + xx*2;
                s = (p[0] + p[1] + p[320] + p[321]) / 4.0f;
            }
            float v = (s - mean) / stdv;
            colsum += wy[i]*v;
        }
        acc += wx[j]*colsum;
    }
    dst[(size_t)path*HALF + r] = acc;
}

// ---------------- conv3x3 FFMA (CI=3 first layer) ----------------
__global__ __launch_bounds__(256)
void conv3x3_kernel(const float* __restrict__ in, const float* __restrict__ wT,
                    const float* __restrict__ bias, float* __restrict__ out,
                    int CI, int CO, int H, int W){
    __shared__ float insm[8*4*72];
    __shared__ float wsm [72*64];

    int tid = threadIdx.x;
    int tx = tid & 15;
    int ty = tid >> 4;
    int x0 = blockIdx.x * 64;
    int y0 = blockIdx.y * 2;
    int cog = CO >> 6;
    int b   = blockIdx.z / cog;
    int co0 = (blockIdx.z % cog) << 6;

    float acc[4][2][4];
    #pragma unroll
    for (int i = 0; i < 4; i++)
        #pragma unroll
        for (int r = 0; r < 2; r++)
            #pragma unroll
            for (int j = 0; j < 4; j++) acc[i][r][j] = 0.f;

    const float* inb = in + (size_t)b*CI*H*W;

    for (int ci0 = 0; ci0 < CI; ci0 += 8){
        int cn = CI - ci0; if (cn > 8) cn = 8;
        __syncthreads();
        int nin = cn*264;
        for (int s = tid; s < nin; s += 256){
            int ci  = s / 264;
            int rem = s - ci*264;
            int r   = rem / 66;
            int xx  = rem - r*66;
            int gy = y0 + r - 1;
            int gx = x0 + xx - 1;
            float v = 0.f;
            if (gy >= 0 && gy < H && gx >= 0 && gx < W)
                v = inb[((size_t)(ci0+ci)*H + gy)*W + gx];
            insm[(ci*4 + r)*72 + xx] = v;
        }
        int kk = cn*9;
        for (int s = tid; s < kk*64; s += 256){
            int k  = s >> 6;
            int co = s & 63;
            wsm[k*64 + co] = wT[((size_t)ci0*9 + k)*CO + co0 + co];
        }
        __syncthreads();

        float accc[4][2][4];
        #pragma unroll
        for (int i = 0; i < 4; i++)
            #pragma unroll
            for (int r = 0; r < 2; r++)
                #pragma unroll
                for (int j = 0; j < 4; j++) accc[i][r][j] = 0.f;

        for (int ci = 0; ci < cn; ci++){
            #pragma unroll
            for (int dy = 0; dy < 3; dy++){
                const float* ipa = &insm[(ci*4 + dy)*72 + tx*4];
                float a6[6], b6[6];
                #pragma unroll
                for (int u = 0; u < 6; u++){ a6[u] = ipa[u]; b6[u] = ipa[72+u]; }
                #pragma unroll
                for (int dx = 0; dx < 3; dx++){
                    float4 wv = *(const float4*)&wsm[(ci*9 + dy*3 + dx)*64 + ty*4];
                    #pragma unroll
                    for (int j = 0; j < 4; j++){
                        float ia = a6[dx + j];
                        float ib = b6[dx + j];
                        accc[0][0][j] += wv.x * ia;  accc[0][1][j] += wv.x * ib;
                        accc[1][0][j] += wv.y * ia;  accc[1][1][j] += wv.y * ib;
                        accc[2][0][j] += wv.z * ia;  accc[2][1][j] += wv.z * ib;
                        accc[3][0][j] += wv.w * ia;  accc[3][1][j] += wv.w * ib;
                    }
                }
            }
        }
        #pragma unroll
        for (int i = 0; i < 4; i++)
            #pragma unroll
            for (int r = 0; r < 2; r++)
                #pragma unroll
                for (int j = 0; j < 4; j++) acc[i][r][j] += accc[i][r][j];
    }

    #pragma unroll
    for (int i = 0; i < 4; i++){
        int co = co0 + ty*4 + i;
        float bv = bias[co];
        #pragma unroll
        for (int r = 0; r < 2; r++){
            #pragma unroll
            for (int j = 0; j < 4; j++){
                int x = x0 + tx*4 + j;
                if (x < W){
                    float v = acc[i][r][j] + bv;
                    out[(((size_t)b*CO + co)*H + (y0+r))*W + x] = fmaxf(v, 0.f);
                }
            }
        }
    }
}

// ---------------- conv3x3 3xTF32, 2 rows/block, cp.async pipelined, 2 CTAs/SM ----------------
#define ISM_N   (8*4*84)
#define STG_N   (8*4*82)
#define WSM_N   (9*8*65)
#define CONV_SMEM_FLOATS (2*ISM_N + 2*STG_N + 2*WSM_N)

__global__ __launch_bounds__(256, 2)
void conv3x3_tf32_kernel(const float* __restrict__ in, const float* __restrict__ wT,
                         const float* __restrict__ bias, float* __restrict__ out,
                         int CI, int CO, int H, int W){
    extern __shared__ float csm[];
    float* ismh = csm;
    float* isml = ismh + ISM_N;
    float* stg  = isml + ISM_N;          // [2][STG_N]
    float* wsm  = stg + 2*STG_N;         // [2][WSM_N]

    int tid  = threadIdx.x;
    int warp = tid >> 5, lane = tid & 31;
    int wm = warp & 3;
    int wn = warp >> 2;
    int g  = lane >> 2;
    int q  = lane & 3;

    int x0 = blockIdx.x * 80;
    int y0 = blockIdx.y * 2;
    int cog = CO >> 6;
    int b   = blockIdx.z / cog;
    int co0 = (blockIdx.z % cog) << 6;

    const float* inb = in + (size_t)b*CI*H*W;
    uint32_t stg_base = smem_u32(stg);
    uint32_t wsm_base = smem_u32(wsm);

    float cacc[2][5][4];
    #pragma unroll
    for (int r = 0; r < 2; r++)
        #pragma unroll
        for (int nt = 0; nt < 5; nt++)
            #pragma unroll
            for (int i = 0; i < 4; i++) cacc[r][nt][i] = 0.f;

    int nch = CI >> 3;

    auto issue_chunk = [&](int ci0, int buf){
        for (int s = tid; s < STG_N; s += 256){
            int ci  = s / 328;
            int rem = s - ci*328;
            int r   = rem / 82;
            int col = rem - r*82;
            int gy = y0 + r - 1;
            int gx = x0 + col - 1;
            bool ok = (gy >= 0 && gy < H && gx >= 0 && gx < W);
            const float* gp = ok ? (inb + ((size_t)(ci0+ci)*H + gy)*W + gx) : inb;
            cp_async4(stg_base + (uint32_t)(buf*STG_N + s)*4u, gp, ok);
        }
        for (int s = tid; s < 9*8*64; s += 256){
            int tap = s >> 9;
            int rem = s & 511;
            int ci  = rem >> 6;
            int co  = rem & 63;
            cp_async4(wsm_base + (uint32_t)(buf*WSM_N + (tap*8+ci)*65 + co)*4u,
                      wT + ((size_t)(ci0+ci)*9 + tap)*CO + co0 + co, true);
        }
        CP_COMMIT();
    };

    issue_chunk(0, 0);

    for (int c = 0; c < nch; c++){
        int buf = c & 1;
        CP_WAIT0();          // chunk c fully landed
        __syncthreads();     // all threads done with prev compute; chunk c visible

        const float* sb = stg + buf*STG_N;
        for (int s = tid; s < STG_N; s += 256){
            int ci  = s / 328;
            int rem = s - ci*328;
            int r   = rem / 82;
            int col = rem - r*82;
            uint32_t h, l;
            split_tf32(sb[s], h, l);
            ismh[(ci*4 + r)*84 + col] = __uint_as_float(h);
            isml[(ci*4 + r)*84 + col] = __uint_as_float(l);
        }
        __syncthreads();     // split visible; safe to overwrite buf^1

        if (c + 1 < nch) issue_chunk((c+1)*8, buf^1);

        const float* wp = wsm + buf*WSM_N;
        #pragma unroll
        for (int dy = 0; dy < 3; dy++){
            #pragma unroll
            for (int dx = 0; dx < 3; dx++){
                int tap = dy*3 + dx;
                float a0 = wp[(tap*8 + q  )*65 + wm*16 + g    ];
                float a1 = wp[(tap*8 + q  )*65 + wm*16 + g + 8];
                float a2 = wp[(tap*8 + q+4)*65 + wm*16 + g    ];
                float a3 = wp[(tap*8 + q+4)*65 + wm*16 + g + 8];
                uint32_t ah0,al0,ah1,al1,ah2,al2,ah3,al3;
                split_tf32(a0, ah0, al0);
                split_tf32(a1, ah1, al1);
                split_tf32(a2, ah2, al2);
                split_tf32(a3, ah3, al3);
                #pragma unroll
                for (int r = 0; r < 2; r++){
                    #pragma unroll
                    for (int nt = 0; nt < 5; nt++){
                        int col = wn*40 + nt*8 + g + dx;
                        int i0 = ( q   *4 + r + dy)*84 + col;
                        int i1 = ((q+4)*4 + r + dy)*84 + col;
                        uint32_t bh0 = __float_as_uint(ismh[i0]);
                        uint32_t bh1 = __float_as_uint(ismh[i1]);
                        uint32_t bl0 = __float_as_uint(isml[i0]);
                        uint32_t bl1 = __float_as_uint(isml[i1]);
                        mma_tf32(cacc[r][nt], al0,al1,al2,al3, bh0,bh1);
                        mma_tf32(cacc[r][nt], ah0,ah1,ah2,ah3, bl0,bl1);
                        mma_tf32(cacc[r][nt], ah0,ah1,ah2,ah3, bh0,bh1);
                    }
                }
            }
        }
    }

    int coA = co0 + wm*16 + g;
    int coB = coA + 8;
    float bvA = bias[coA], bvB = bias[coB];
    #pragma unroll
    for (int r = 0; r < 2; r++){
        float* outA = out + (((size_t)b*CO + coA)*H + (y0+r))*W;
        float* outB = out + (((size_t)b*CO + coB)*H + (y0+r))*W;
        #pragma unroll
        for (int nt = 0; nt < 5; nt++){
            int x = x0 + wn*40 + nt*8 + 2*q;
            outA[x  ] = fmaxf(cacc[r][nt][0] + bvA, 0.f);
            outA[x+1] = fmaxf(cacc[r][nt][1] + bvA, 0.f);
            outB[x  ] = fmaxf(cacc[r][nt][2] + bvB, 0.f);
            outB[x+1] = fmaxf(cacc[r][nt][3] + bvB, 0.f);
        }
    }
}

// ---------------- 1x1 map conv (128 -> 16) + LeakyReLU(0.2), B=4 ----------------
__global__ void conv1x1_leaky_kernel(const float* __restrict__ in, const float* __restrict__ w,
                                     const float* __restrict__ bias, float* __restrict__ out){
    int t = blockIdx.x*blockDim.x + threadIdx.x;
    if (t >= 4*16*6400) return;
    int px = t % 6400;
    int co = (t / 6400) % 16;
    int b  = t / (6400*16);
    const float* ip = in + (size_t)b*128*6400 + px;
    const float* wp = w + co*128;
    float s = 0.f;
    for (int c0 = 0; c0 < 128; c0 += 16){
        float sc = 0.f;
        #pragma unroll
        for (int ci = 0; ci < 16; ci++) sc += ip[(size_t)(c0+ci)*6400] * wp[c0+ci];
        s += sc;
    }
    s += bias[co];
    out[t] = s > 0.f ? s : 0.2f*s;
}

// ---------------- 3x3 unfold (reflect pad) + per-position L2 normalize, B=4 ----------------
__global__ void patches_norm_kernel(const float* __restrict__ f, float* __restrict__ P){
    int t = blockIdx.x*blockDim.x + threadIdx.x;
    if (t >= 4*6400) return;
    int m = t % 6400;
    int b = t / 6400;
    int y = m / 80, x = m % 80;
    int ry[3], rx[3];
    #pragma unroll
    for (int i = 0; i < 3; i++){
        int yy = y + i - 1; ry[i] = yy < 0 ? -yy : (yy > 79 ? 158 - yy : yy);
        int xx = x + i - 1; rx[i] = xx < 0 ? -xx : (xx > 79 ? 158 - xx : xx);
    }
    const float* fb = f + (size_t)b*16*6400;
    float ss = 0.f;
    for (int c = 0; c < 16; c++){
        const float* fc = fb + c*6400;
        float sc = 0.f;
        #pragma unroll
        for (int i = 0; i < 3; i++)
            #pragma unroll
            for (int j = 0; j < 3; j++){
                float v = fc[ry[i]*80 + rx[j]];
                sc += v*v;
            }
        ss += sc;
    }
    float nrm = fmaxf(sqrtf(ss), 1e-12f);
    float* Pb = P + (size_t)b*144*6400;
    for (int c = 0; c < 16; c++){
        const float* fc = fb + c*6400;
        #pragma unroll
        for (int i = 0; i < 3; i++)
            #pragma unroll
            for (int j = 0; j < 3; j++)
                Pb[(size_t)(c*9 + i*3 + j)*6400 + m] = fc[ry[i]*80 + rx[j]] / nrm;
    }
}

// ---------------- cosine-sim via 3xTF32 mma v2 + streaming max/argmax ----------------
#define QSTR 68
#define KSTR 132
__global__ __launch_bounds__(256)
void match_tf32_kernel(const uint32_t* __restrict__ Ph, const uint32_t* __restrict__ Pl,
                       float* __restrict__ mv, int* __restrict__ mi){
    extern __shared__ float dsm[];
    float* qh = dsm;
    float* ql = qh + 144*QSTR;
    float* kh = ql + 144*QSTR;
    float* kl = kh + 16*KSTR;

    int b    = blockIdx.y;
    int half = blockIdx.z;
    int m0   = blockIdx.x * 64;
    int tid  = threadIdx.x;
    int warp = tid >> 5, lane = tid & 31;
    int kw = warp & 3;
    int qw = warp >> 2;
    int g  = lane >> 2;
    int q  = lane & 3;

    const uint32_t* Qhb = Ph + (size_t)b*144*6400;
    const uint32_t* Qlb = Pl + (size_t)b*144*6400;
    const uint32_t* Khb = Ph + (size_t)(2+b)*144*6400;
    const uint32_t* Klb = Pl + (size_t)(2+b)*144*6400;

    for (int s = tid; s < 144*64; s += 256){
        int c = s >> 6, mm = s & 63;
        qh[c*QSTR + mm] = __uint_as_float(Qhb[(size_t)c*6400 + m0 + mm]);
        ql[c*QSTR + mm] = __uint_as_float(Qlb[(size_t)c*6400 + m0 + mm]);
    }

    float bestv[8];
    int   besti[8];
    #pragma unroll
    for (int i = 0; i < 8; i++){ bestv[i] = -FLT_MAX; besti[i] = 0; }

    int lbeg = half*3200, lend = lbeg + 3200;
    for (int l0 = lbeg; l0 < lend; l0 += 128){
        float acc[2][4][4];
        #pragma unroll
        for (int mf = 0; mf < 2; mf++)
            #pragma unroll
            for (int nf = 0; nf < 4; nf++)
                #pragma unroll
                for (int i = 0; i < 4; i++) acc[mf][nf][i] = 0.f;

        for (int c0 = 0; c0 < 144; c0 += 16){
            __syncthreads();
            for (int s = tid; s < 16*128; s += 256){
                int cc = s >> 7, ll = s & 127;
                kh[cc*KSTR + ll] = __uint_as_float(Khb[(size_t)(c0+cc)*6400 + l0 + ll]);
                kl[cc*KSTR + ll] = __uint_as_float(Klb[(size_t)(c0+cc)*6400 + l0 + ll]);
            }
            __syncthreads();

            #pragma unroll
            for (int kf = 0; kf < 2; kf++){
                int cr0 = kf*8 + q;
                int cr1 = kf*8 + q + 4;
                uint32_t ah[2][4], al[2][4];
                #pragma unroll
                for (int mf = 0; mf < 2; mf++){
                    int kr = kw*32 + mf*16;
                    ah[mf][0] = __float_as_uint(kh[cr0*KSTR + kr + g    ]);
                    ah[mf][1] = __float_as_uint(kh[cr0*KSTR + kr + g + 8]);
                    ah[mf][2] = __float_as_uint(kh[cr1*KSTR + kr + g    ]);
                    ah[mf][3] = __float_as_uint(kh[cr1*KSTR + kr + g + 8]);
                    al[mf][0] = __float_as_uint(kl[cr0*KSTR + kr + g    ]);
                    al[mf][1] = __float_as_uint(kl[cr0*KSTR + kr + g + 8]);
                    al[mf][2] = __float_as_uint(kl[cr1*KSTR + kr + g    ]);
                    al[mf][3] = __float_as_uint(kl[cr1*KSTR + kr + g + 8]);
                }
                #pragma unroll
                for (int nf = 0; nf < 4; nf++){
                    int col = qw*32 + nf*8 + g;
                    uint32_t bh0 = __float_as_uint(qh[(c0+cr0)*QSTR + col]);
                    uint32_t bh1 = __float_as_uint(qh[(c0+cr1)*QSTR + col]);
                    uint32_t bl0 = __float_as_uint(ql[(c0+cr0)*QSTR + col]);
                    uint32_t bl1 = __float_as_uint(ql[(c0+cr1)*QSTR + col]);
                    #pragma unroll
                    for (int mf = 0; mf < 2; mf++){
                        mma_tf32(acc[mf][nf], al[mf][0],al[mf][1],al[mf][2],al[mf][3], bh0,bh1);
                        mma_tf32(acc[mf][nf], ah[mf][0],ah[mf][1],ah[mf][2],ah[mf][3], bl0,bl1);
                        mma_tf32(acc[mf][nf], ah[mf][0],ah[mf][1],ah[mf][2],ah[mf][3], bh0,bh1);
                    }
                }
            }
        }

        #pragma unroll
        for (int mf = 0; mf < 2; mf++){
            int keyA = l0 + kw*32 + mf*16 + g;
            int keyB = keyA + 8;
            #pragma unroll
            for (int nf = 0; nf < 4; nf++){
                #pragma unroll
                for (int p = 0; p < 2; p++){
                    int sl = nf*2 + p;
                    float vA = acc[mf][nf][p];
                    float vB = acc[mf][nf][2+p];
                    if (vA > bestv[sl]){ bestv[sl] = vA; besti[sl] = keyA; }
                    if (vB > bestv[sl]){ bestv[sl] = vB; besti[sl] = keyB; }
                }
            }
        }
    }

    __syncthreads();
    float* sv = kh;
    float* si = kl;
    #pragma unroll
    for (int nf = 0; nf < 4; nf++)
        #pragma unroll
        for (int p = 0; p < 2; p++){
            int qcol = qw*32 + nf*8 + 2*q + p;
            int sl   = nf*2 + p;
            sv[qcol*32 + kw*8 + g] = bestv[sl];
            si[qcol*32 + kw*8 + g] = __int_as_float(besti[sl]);
        }
    __syncthreads();
    if (tid < 64){
        float bv = -FLT_MAX; int bi = 0x7fffffff;
        for (int t2 = 0; t2 < 32; t2++){
            float v  = sv[tid*32 + t2];
            int   ix = __float_as_int(si[tid*32 + t2]);
            if (v > bv || (v == bv && ix < bi)){ bv = v; bi = ix; }
        }
        int m = m0 + tid;
        mv[((size_t)half*BA + b)*6400 + m] = bv;
        mi[((size_t)half*BA + b)*6400 + m] = bi;
    }
}

// ---------------- merge two k-halves ----------------
__global__ void merge_kernel(const float* __restrict__ mv, const int* __restrict__ mi,
                             float* __restrict__ outp){
    int t = blockIdx.x*blockDim.x + threadIdx.x;
    if (t >= BA*6400) return;
    float v0 = mv[t], v1 = mv[BA*6400 + t];
    int   i0 = mi[t], i1 = mi[BA*6400 + t];
    float v = v0; int i = i0;
    if (v1 > v0){ v = v1; i = i1; }
    outp[t]             = v;
    outp[BA*6400 + t]   = (float)i;
}

extern "C" void kernel_launch(void* const* d_in, const int* in_sizes, int n_in,
                              void* d_out, int out_size){
    (void)in_sizes; (void)n_in; (void)out_size;
    const float* query = (const float*)d_in[0];
    const float* key   = (const float*)d_in[1];
    const float* w1 = (const float*)d_in[2];  const float* b1 = (const float*)d_in[3];
    const float* w2 = (const float*)d_in[4];  const float* b2 = (const float*)d_in[5];
    const float* w3 = (const float*)d_in[6];  const float* b3 = (const float*)d_in[7];
    const float* w4 = (const float*)d_in[8];  const float* b4 = (const float*)d_in[9];
    const float* wm = (const float*)d_in[10]; const float* bm = (const float*)d_in[11];
    float* out = (float*)d_out;

    float *up, *bufA, *bufB, *feat, *P, *wT, *mv;
    uint32_t *Ph, *Pl;
    int *mi;
    cudaGetSymbolAddress((void**)&up,     g_up);
    cudaGetSymbolAddress((void**)&bufA,   g_bufA);
    cudaGetSymbolAddress((void**)&bufB,   g_bufB);
    cudaGetSymbolAddress((void**)&feat,   g_feat);
    cudaGetSymbolAddress((void**)&P,      g_P);
    cudaGetSymbolAddress((void**)&Ph,     g_Ph);
    cudaGetSymbolAddress((void**)&Pl,     g_Pl);
    cudaGetSymbolAddress((void**)&wT,     g_wT);
    cudaGetSymbolAddress((void**)&mv,     g_mv);
    cudaGetSymbolAddress((void**)&mi,     g_mi);

    size_t conv_smem = CONV_SMEM_FLOATS * sizeof(float);   // ~80 KB
    cudaFuncSetAttribute(conv3x3_tf32_kernel,
                         cudaFuncAttributeMaxDynamicSharedMemorySize, (int)conv_smem);

    transw_all_kernel<<<(259776+255)/256,256>>>(w1, w2, w3, w4, wT);
    upsample_both_kernel<<<(2*BA*3*320*320+255)/256,256>>>(query, key, up);

    conv3x3_kernel<<<dim3(5,160,4*1),256>>>(up,   wT+OFF_W1, b1, bufA, 3,  64, 320, 320);
    // conv2 tf32 remains overall launch #6 = ncu capture slot
    conv3x3_tf32_kernel<<<dim3(4,160,4*1),256,conv_smem>>>(bufA, wT+OFF_W2, b2, bufB, 64, 64, 320, 320);
    maxpool2_kernel<<<(4*64*160*160+255)/256,256>>>(bufB, bufA, 4*64*160*160, 160, 160);
    conv3x3_tf32_kernel<<<dim3(2,80,4*2),256,conv_smem>>>(bufA, wT+OFF_W3, b3, bufB, 64, 128, 160, 160);
    conv3x3_tf32_kernel<<<dim3(2,80,4*2),256,conv_smem>>>(bufB, wT+OFF_W4, b4, bufA, 128,128, 160, 160);
    maxpool2_kernel<<<(4*128*80*80+255)/256,256>>>(bufA, bufB, 4*128*80*80, 80, 80);
    conv1x1_leaky_kernel<<<(4*16*6400+255)/256,256>>>(bufB, wm, bm, feat);

    patches_norm_kernel<<<(4*6400+255)/256,256>>>(feat, P);
    psplit_kernel<<<(4*144*6400+255)/256,256>>>(P, Ph, Pl);

    size_t match_smem = (2*144*QSTR + 2*16*KSTR) * sizeof(float);   // ~95 KB
    cudaFuncSetAttribute(match_tf32_kernel,
                         cudaFuncAttributeMaxDynamicSharedMemorySize, (int)match_smem);
    match_tf32_kernel<<<dim3(100,BA,2),256,match_smem>>>(Ph, Pl, mv, mi);
    merge_kernel<<<(BA*6400+255)/256,256>>>(mv, mi, out);
}

// round 16
// speedup vs baseline: 1.3252x; 1.0579x over previous
#include <cuda_runtime.h>
#include <cstdint>
#include <cfloat>
#include <math.h>

#define BA 2
#define A_COEF (-0.75f)

__constant__ float c_mean[3] = {0.485f, 0.456f, 0.406f};
__constant__ float c_std[3]  = {0.229f, 0.224f, 0.225f};

// ---------------- scratch (static device memory) ----------------
__device__ float    g_up   [4*3*320*320];
__device__ float    g_bufA [4*64*320*320];
__device__ float    g_bufB [4*64*320*320];
__device__ float    g_feat [4*16*80*80];
__device__ float    g_P    [4*144*6400];
__device__ uint32_t g_Ph   [4*144*6400];
__device__ uint32_t g_Pl   [4*144*6400];
__device__ float    g_wT   [259776];
__device__ float    g_mv   [2*BA*6400];
__device__ int      g_mi   [2*BA*6400];

#define OFF_W1 0
#define OFF_W2 1728
#define OFF_W3 38592
#define OFF_W4 112320

__device__ __forceinline__ float cubicw(float d){
    d = fabsf(d);
    if (d <= 1.f) return ((A_COEF + 2.f)*d - (A_COEF + 3.f))*d*d + 1.f;
    if (d < 2.f)  return A_COEF*(((d - 5.f)*d + 8.f)*d - 4.f);
    return 0.f;
}

// ---------------- tf32 helpers ----------------
__device__ __forceinline__ void split_tf32(float x, uint32_t& hi, uint32_t& lo){
    uint32_t h;
    asm("cvt.rna.tf32.f32 %0, %1;" : "=r"(h) : "f"(x));
    float l = x - __uint_as_float(h);
    uint32_t lr;
    asm("cvt.rna.tf32.f32 %0, %1;" : "=r"(lr) : "f"(l));
    hi = h; lo = lr;
}

__device__ __forceinline__ void mma_tf32(float* c,
        uint32_t a0, uint32_t a1, uint32_t a2, uint32_t a3,
        uint32_t b0, uint32_t b1){
    asm volatile("mma.sync.aligned.m16n8k8.row.col.f32.tf32.tf32.f32 "
        "{%0,%1,%2,%3}, {%4,%5,%6,%7}, {%8,%9}, {%0,%1,%2,%3};"
        : "+f"(c[0]),"+f"(c[1]),"+f"(c[2]),"+f"(c[3])
        : "r"(a0),"r"(a1),"r"(a2),"r"(a3), "r"(b0),"r"(b1));
}

// ---------------- cp.async helpers ----------------
__device__ __forceinline__ uint32_t smem_u32(const void* p){
    return (uint32_t)__cvta_generic_to_shared(p);
}
__device__ __forceinline__ void cp_async4(uint32_t saddr, const void* gptr, bool pred){
    int sz = pred ? 4 : 0;
    asm volatile("cp.async.ca.shared.global [%0], [%1], 4, %2;\n"
        :: "r"(saddr), "l"(gptr), "r"(sz));
}
#define CP_COMMIT()  asm volatile("cp.async.commit_group;\n" ::)
#define CP_WAIT0()   asm volatile("cp.async.wait_group 0;\n" ::)

// ---------------- merged weight transpose ----------------
__global__ void transw_all_kernel(const float* __restrict__ w1, const float* __restrict__ w2,
                                  const float* __restrict__ w3, const float* __restrict__ w4,
                                  float* __restrict__ wT){
    int t = blockIdx.x*blockDim.x + threadIdx.x;
    if (t >= 259776) return;
    const float* w; int CO, CI, base;
    if (t < 38592){
        if (t < 1728){ w = w1; CO = 64;  CI = 3;   base = OFF_W1; }
        else         { w = w2; CO = 64;  CI = 64;  base = OFF_W2; }
    } else {
        if (t < 112320){ w = w3; CO = 128; CI = 64;  base = OFF_W3; }
        else           { w = w4; CO = 128; CI = 128; base = OFF_W4; }
    }
    int loc = t - base;
    int co  = loc / (CI*9);
    int r   = loc - co*(CI*9);
    wT[base + r*CO + co] = w[loc];
}

// ---------------- P tf32 pre-split ----------------
__global__ void psplit_kernel(const float* __restrict__ P, uint32_t* __restrict__ Ph,
                              uint32_t* __restrict__ Pl){
    int t = blockIdx.x*blockDim.x + threadIdx.x;
    if (t >= 4*144*6400) return;
    uint32_t h, l;
    split_tf32(P[t], h, l);
    Ph[t] = h; Pl[t] = l;
}

// ---------------- maxpool 2x2 stride 2 ----------------
__global__ void maxpool2_kernel(const float* __restrict__ in, float* __restrict__ out,
                                int total, int H2, int W2){
    int t = blockIdx.x*blockDim.x + threadIdx.x;
    if (t >= total) return;
    int x  = t % W2;
    int y  = (t / W2) % H2;
    int bc = t / (W2*H2);
    const float* p = in + (((size_t)bc*(H2*2)) + y*2)*(W2*2) + x*2;
    out[t] = fmaxf(fmaxf(p[0], p[1]), fmaxf(p[W2*2], p[W2*2+1]));
}

// ---------------- merged: sub_mean + bicubic upsample x2 for BOTH paths ----------------
__global__ void upsample_both_kernel(const float* __restrict__ query,
                                     const float* __restrict__ key,
                                     float* __restrict__ dst){
    const int HALF = BA*3*320*320;
    int t = blockIdx.x*blockDim.x + threadIdx.x;
    if (t >= 2*HALF) return;
    int path = t / HALF;
    int r    = t - path*HALF;
    int ox = r % 320;
    int oy = (r / 320) % 320;
    int c  = (r / (320*320)) % 3;
    int b  = r / (320*320*3);

    const int Hs = 160, Ws = 160;
    float sy = (float)((double)(Hs-1) / 319.0);
    float sx = (float)((double)(Ws-1) / 319.0);
    float cy = (float)oy * sy;
    float cx = (float)ox * sx;
    float fy = floorf(cy), fx = floorf(cx);
    float tv = cy - fy,    tu = cx - fx;
    int iy = (int)fy, ix = (int)fx;

    float wy[4] = {cubicw(tv+1.f), cubicw(tv), cubicw(tv-1.f), cubicw(tv-2.f)};
    float wx[4] = {cubicw(tu+1.f), cubicw(tu), cubicw(tu-1.f), cubicw(tu-2.f)};

    float mean = c_mean[c], stdv = c_std[c];
    const float* qp = query + ((size_t)b*3 + c)*Hs*Ws;
    const float* kp = key   + ((size_t)b*3 + c)*320*320;

    float acc = 0.f;
    #pragma unroll
    for (int j = 0; j < 4; j++){
        int xx = ix - 1 + j;
        xx = xx < 0 ? 0 : (xx > Ws-1 ? Ws-1 : xx);
        float colsum = 0.f;
        #pragma unroll
        for (int i = 0; i < 4; i++){
            int yy = iy - 1 + i;
            yy = yy < 0 ? 0 : (yy > Hs-1 ? Hs-1 : yy);
            float s;
            if (path == 0){
                s = qp[yy*Ws + xx];
            } else {
                const float* p = kp + (yy*2)*320 + xx*2;
                s = (p[0] + p[1] + p[320] + p[321]) / 4.0f;
            }
            float v = (s - mean) / stdv;
            colsum += wy[i]*v;
        }
        acc += wx[j]*colsum;
    }
    dst[(size_t)path*HALF + r] = acc;
}

// ---------------- conv3x3 FFMA (CI=3 first layer) ----------------
__global__ __launch_bounds__(256)
void conv3x3_kernel(const float* __restrict__ in, const float* __restrict__ wT,
                    const float* __restrict__ bias, float* __restrict__ out,
                    int CI, int CO, int H, int W){
    __shared__ float insm[8*4*72];
    __shared__ float wsm [72*64];

    int tid = threadIdx.x;
    int tx = tid & 15;
    int ty = tid >> 4;
    int x0 = blockIdx.x * 64;
    int y0 = blockIdx.y * 2;
    int cog = CO >> 6;
    int b   = blockIdx.z / cog;
    int co0 = (blockIdx.z % cog) << 6;

    float acc[4][2][4];
    #pragma unroll
    for (int i = 0; i < 4; i++)
        #pragma unroll
        for (int r = 0; r < 2; r++)
            #pragma unroll
            for (int j = 0; j < 4; j++) acc[i][r][j] = 0.f;

    const float* inb = in + (size_t)b*CI*H*W;

    for (int ci0 = 0; ci0 < CI; ci0 += 8){
        int cn = CI - ci0; if (cn > 8) cn = 8;
        __syncthreads();
        int nin = cn*264;
        for (int s = tid; s < nin; s += 256){
            int ci  = s / 264;
            int rem = s - ci*264;
            int r   = rem / 66;
            int xx  = rem - r*66;
            int gy = y0 + r - 1;
            int gx = x0 + xx - 1;
            float v = 0.f;
            if (gy >= 0 && gy < H && gx >= 0 && gx < W)
                v = inb[((size_t)(ci0+ci)*H + gy)*W + gx];
            insm[(ci*4 + r)*72 + xx] = v;
        }
        int kk = cn*9;
        for (int s = tid; s < kk*64; s += 256){
            int k  = s >> 6;
            int co = s & 63;
            wsm[k*64 + co] = wT[((size_t)ci0*9 + k)*CO + co0 + co];
        }
        __syncthreads();

        float accc[4][2][4];
        #pragma unroll
        for (int i = 0; i < 4; i++)
            #pragma unroll
            for (int r = 0; r < 2; r++)
                #pragma unroll
                for (int j = 0; j < 4; j++) accc[i][r][j] = 0.f;

        for (int ci = 0; ci < cn; ci++){
            #pragma unroll
            for (int dy = 0; dy < 3; dy++){
                const float* ipa = &insm[(ci*4 + dy)*72 + tx*4];
                float a6[6], b6[6];
                #pragma unroll
                for (int u = 0; u < 6; u++){ a6[u] = ipa[u]; b6[u] = ipa[72+u]; }
                #pragma unroll
                for (int dx = 0; dx < 3; dx++){
                    float4 wv = *(const float4*)&wsm[(ci*9 + dy*3 + dx)*64 + ty*4];
                    #pragma unroll
                    for (int j = 0; j < 4; j++){
                        float ia = a6[dx + j];
                        float ib = b6[dx + j];
                        accc[0][0][j] += wv.x * ia;  accc[0][1][j] += wv.x * ib;
                        accc[1][0][j] += wv.y * ia;  accc[1][1][j] += wv.y * ib;
                        accc[2][0][j] += wv.z * ia;  accc[2][1][j] += wv.z * ib;
                        accc[3][0][j] += wv.w * ia;  accc[3][1][j] += wv.w * ib;
                    }
                }
            }
        }
        #pragma unroll
        for (int i = 0; i < 4; i++)
            #pragma unroll
            for (int r = 0; r < 2; r++)
                #pragma unroll
                for (int j = 0; j < 4; j++) acc[i][r][j] += accc[i][r][j];
    }

    #pragma unroll
    for (int i = 0; i < 4; i++){
        int co = co0 + ty*4 + i;
        float bv = bias[co];
        #pragma unroll
        for (int r = 0; r < 2; r++){
            #pragma unroll
            for (int j = 0; j < 4; j++){
                int x = x0 + tx*4 + j;
                if (x < W){
                    float v = acc[i][r][j] + bv;
                    out[(((size_t)b*CO + co)*H + (y0+r))*W + x] = fmaxf(v, 0.f);
                }
            }
        }
    }
}

// ---------------- conv3x3 3xTF32, 2 rows/block, cp.async pipelined, 2 CTAs/SM ----------------
#define ISM_N   (8*4*84)
#define STG_N   (8*4*82)
#define WSM_N   (9*8*65)
#define CONV_SMEM_FLOATS (2*ISM_N + 2*STG_N + 2*WSM_N)

__global__ __launch_bounds__(256, 2)
void conv3x3_tf32_kernel(const float* __restrict__ in, const float* __restrict__ wT,
                         const float* __restrict__ bias, float* __restrict__ out,
                         int CI, int CO, int H, int W){
    extern __shared__ float csm[];
    float* ismh = csm;
    float* isml = ismh + ISM_N;
    float* stg  = isml + ISM_N;          // [2][STG_N]
    float* wsm  = stg + 2*STG_N;         // [2][WSM_N]

    int tid  = threadIdx.x;
    int warp = tid >> 5, lane = tid & 31;
    int wm = warp & 3;
    int wn = warp >> 2;
    int g  = lane >> 2;
    int q  = lane & 3;

    int x0 = blockIdx.x * 80;
    int y0 = blockIdx.y * 2;
    int cog = CO >> 6;
    int b   = blockIdx.z / cog;
    int co0 = (blockIdx.z % cog) << 6;

    const float* inb = in + (size_t)b*CI*H*W;
    uint32_t stg_base = smem_u32(stg);
    uint32_t wsm_base = smem_u32(wsm);

    float cacc[2][5][4];
    #pragma unroll
    for (int r = 0; r < 2; r++)
        #pragma unroll
        for (int nt = 0; nt < 5; nt++)
            #pragma unroll
            for (int i = 0; i < 4; i++) cacc[r][nt][i] = 0.f;

    int nch = CI >> 3;

    auto issue_chunk = [&](int ci0, int buf){
        for (int s = tid; s < STG_N; s += 256){
            int ci  = s / 328;
            int rem = s - ci*328;
            int r   = rem / 82;
            int col = rem - r*82;
            int gy = y0 + r - 1;
            int gx = x0 + col - 1;
            bool ok = (gy >= 0 && gy < H && gx >= 0 && gx < W);
            const float* gp = ok ? (inb + ((size_t)(ci0+ci)*H + gy)*W + gx) : inb;
            cp_async4(stg_base + (uint32_t)(buf*STG_N + s)*4u, gp, ok);
        }
        for (int s = tid; s < 9*8*64; s += 256){
            int tap = s >> 9;
            int rem = s & 511;
            int ci  = rem >> 6;
            int co  = rem & 63;
            cp_async4(wsm_base + (uint32_t)(buf*WSM_N + (tap*8+ci)*65 + co)*4u,
                      wT + ((size_t)(ci0+ci)*9 + tap)*CO + co0 + co, true);
        }
        CP_COMMIT();
    };

    issue_chunk(0, 0);

    for (int c = 0; c < nch; c++){
        int buf = c & 1;
        CP_WAIT0();
        __syncthreads();

        const float* sb = stg + buf*STG_N;
        for (int s = tid; s < STG_N; s += 256){
            int ci  = s / 328;
            int rem = s - ci*328;
            int r   = rem / 82;
            int col = rem - r*82;
            uint32_t h, l;
            split_tf32(sb[s], h, l);
            ismh[(ci*4 + r)*84 + col] = __uint_as_float(h);
            isml[(ci*4 + r)*84 + col] = __uint_as_float(l);
        }
        __syncthreads();

        if (c + 1 < nch) issue_chunk((c+1)*8, buf^1);

        const float* wp = wsm + buf*WSM_N;
        #pragma unroll
        for (int dy = 0; dy < 3; dy++){
            #pragma unroll
            for (int dx = 0; dx < 3; dx++){
                int tap = dy*3 + dx;
                float a0 = wp[(tap*8 + q  )*65 + wm*16 + g    ];
                float a1 = wp[(tap*8 + q  )*65 + wm*16 + g + 8];
                float a2 = wp[(tap*8 + q+4)*65 + wm*16 + g    ];
                float a3 = wp[(tap*8 + q+4)*65 + wm*16 + g + 8];
                uint32_t ah0,al0,ah1,al1,ah2,al2,ah3,al3;
                split_tf32(a0, ah0, al0);
                split_tf32(a1, ah1, al1);
                split_tf32(a2, ah2, al2);
                split_tf32(a3, ah3, al3);
                #pragma unroll
                for (int r = 0; r < 2; r++){
                    #pragma unroll
                    for (int nt = 0; nt < 5; nt++){
                        int col = wn*40 + nt*8 + g + dx;
                        int i0 = ( q   *4 + r + dy)*84 + col;
                        int i1 = ((q+4)*4 + r + dy)*84 + col;
                        uint32_t bh0 = __float_as_uint(ismh[i0]);
                        uint32_t bh1 = __float_as_uint(ismh[i1]);
                        uint32_t bl0 = __float_as_uint(isml[i0]);
                        uint32_t bl1 = __float_as_uint(isml[i1]);
                        mma_tf32(cacc[r][nt], al0,al1,al2,al3, bh0,bh1);
                        mma_tf32(cacc[r][nt], ah0,ah1,ah2,ah3, bl0,bl1);
                        mma_tf32(cacc[r][nt], ah0,ah1,ah2,ah3, bh0,bh1);
                    }
                }
            }
        }
    }

    int coA = co0 + wm*16 + g;
    int coB = coA + 8;
    float bvA = bias[coA], bvB = bias[coB];
    #pragma unroll
    for (int r = 0; r < 2; r++){
        float* outA = out + (((size_t)b*CO + coA)*H + (y0+r))*W;
        float* outB = out + (((size_t)b*CO + coB)*H + (y0+r))*W;
        #pragma unroll
        for (int nt = 0; nt < 5; nt++){
            int x = x0 + wn*40 + nt*8 + 2*q;
            outA[x  ] = fmaxf(cacc[r][nt][0] + bvA, 0.f);
            outA[x+1] = fmaxf(cacc[r][nt][1] + bvA, 0.f);
            outB[x  ] = fmaxf(cacc[r][nt][2] + bvB, 0.f);
            outB[x+1] = fmaxf(cacc[r][nt][3] + bvB, 0.f);
        }
    }
}

// ---------------- 1x1 map conv (128 -> 16) + LeakyReLU(0.2), B=4 ----------------
__global__ void conv1x1_leaky_kernel(const float* __restrict__ in, const float* __restrict__ w,
                                     const float* __restrict__ bias, float* __restrict__ out){
    int t = blockIdx.x*blockDim.x + threadIdx.x;
    if (t >= 4*16*6400) return;
    int px = t % 6400;
    int co = (t / 6400) % 16;
    int b  = t / (6400*16);
    const float* ip = in + (size_t)b*128*6400 + px;
    const float* wp = w + co*128;
    float s = 0.f;
    for (int c0 = 0; c0 < 128; c0 += 16){
        float sc = 0.f;
        #pragma unroll
        for (int ci = 0; ci < 16; ci++) sc += ip[(size_t)(c0+ci)*6400] * wp[c0+ci];
        s += sc;
    }
    s += bias[co];
    out[t] = s > 0.f ? s : 0.2f*s;
}

// ---------------- 3x3 unfold (reflect pad) + per-position L2 normalize, B=4 ----------------
__global__ void patches_norm_kernel(const float* __restrict__ f, float* __restrict__ P){
    int t = blockIdx.x*blockDim.x + threadIdx.x;
    if (t >= 4*6400) return;
    int m = t % 6400;
    int b = t / 6400;
    int y = m / 80, x = m % 80;
    int ry[3], rx[3];
    #pragma unroll
    for (int i = 0; i < 3; i++){
        int yy = y + i - 1; ry[i] = yy < 0 ? -yy : (yy > 79 ? 158 - yy : yy);
        int xx = x + i - 1; rx[i] = xx < 0 ? -xx : (xx > 79 ? 158 - xx : xx);
    }
    const float* fb = f + (size_t)b*16*6400;
    float ss = 0.f;
    for (int c = 0; c < 16; c++){
        const float* fc = fb + c*6400;
        float sc = 0.f;
        #pragma unroll
        for (int i = 0; i < 3; i++)
            #pragma unroll
            for (int j = 0; j < 3; j++){
                float v = fc[ry[i]*80 + rx[j]];
                sc += v*v;
            }
        ss += sc;
    }
    float nrm = fmaxf(sqrtf(ss), 1e-12f);
    float* Pb = P + (size_t)b*144*6400;
    for (int c = 0; c < 16; c++){
        const float* fc = fb + c*6400;
        #pragma unroll
        for (int i = 0; i < 3; i++)
            #pragma unroll
            for (int j = 0; j < 3; j++)
                Pb[(size_t)(c*9 + i*3 + j)*6400 + m] = fc[ry[i]*80 + rx[j]] / nrm;
    }
}

// ---------------- cosine-sim 3xTF32 mma v3: cp.async double-buffered K tiles ----------------
// block: 64 queries x 3200 keys (half). 225 flat chunks (25 key-tiles x 9 c-chunks).
#define QSTR 68
#define KSTR 132
#define KCH  (16*KSTR)     // one K chunk (hi or lo): 2112 floats
__global__ __launch_bounds__(256)
void match_tf32_kernel(const uint32_t* __restrict__ Ph, const uint32_t* __restrict__ Pl,
                       float* __restrict__ mv, int* __restrict__ mi){
    extern __shared__ float dsm[];
    float* qh = dsm;                  // [144][QSTR]
    float* ql = qh + 144*QSTR;
    float* kh = ql + 144*QSTR;        // [2][KCH]
    float* kl = kh + 2*KCH;           // [2][KCH]

    int b    = blockIdx.y;
    int half = blockIdx.z;
    int m0   = blockIdx.x * 64;
    int tid  = threadIdx.x;
    int warp = tid >> 5, lane = tid & 31;
    int kw = warp & 3;
    int qw = warp >> 2;
    int g  = lane >> 2;
    int q  = lane & 3;

    const uint32_t* Qhb = Ph + (size_t)b*144*6400;
    const uint32_t* Qlb = Pl + (size_t)b*144*6400;
    const uint32_t* Khb = Ph + (size_t)(2+b)*144*6400;
    const uint32_t* Klb = Pl + (size_t)(2+b)*144*6400;

    uint32_t kh_base = smem_u32(kh);
    uint32_t kl_base = smem_u32(kl);
    int lbeg = half*3200;

    // K chunk loader: pure copy (data pre-split in global, L2-resident)
    auto issue_kchunk = [&](int idx, int buf){
        int l0 = lbeg + (idx/9)*128;
        int c0 = (idx - (idx/9)*9)*16;
        for (int s = tid; s < 16*128; s += 256){
            int cc = s >> 7, ll = s & 127;
            size_t go = (size_t)(c0+cc)*6400 + l0 + ll;
            uint32_t so = (uint32_t)(buf*KCH + cc*KSTR + ll)*4u;
            cp_async4(kh_base + so, Khb + go, true);
            cp_async4(kl_base + so, Klb + go, true);
        }
        CP_COMMIT();
    };

    issue_kchunk(0, 0);

    // Q tile load+split (overlaps with first K chunk in flight)
    for (int s = tid; s < 144*64; s += 256){
        int c = s >> 6, mm = s & 63;
        qh[c*QSTR + mm] = __uint_as_float(Qhb[(size_t)c*6400 + m0 + mm]);
        ql[c*QSTR + mm] = __uint_as_float(Qlb[(size_t)c*6400 + m0 + mm]);
    }

    float bestv[8];
    int   besti[8];
    #pragma unroll
    for (int i = 0; i < 8; i++){ bestv[i] = -FLT_MAX; besti[i] = 0; }

    float acc[2][4][4];

    for (int idx = 0; idx < 225; idx++){
        int buf  = idx & 1;
        int lt   = idx / 9;
        int c0i  = idx - lt*9;
        int l0   = lbeg + lt*128;
        int c0   = c0i*16;

        CP_WAIT0();          // chunk idx landed
        __syncthreads();     // all threads past compute(idx-1) (which read buf^1)

        if (idx + 1 < 225) issue_kchunk(idx+1, buf^1);

        if (c0i == 0){
            #pragma unroll
            for (int mf = 0; mf < 2; mf++)
                #pragma unroll
                for (int nf = 0; nf < 4; nf++)
                    #pragma unroll
                    for (int i = 0; i < 4; i++) acc[mf][nf][i] = 0.f;
        }

        const float* khb = kh + buf*KCH;
        const float* klb = kl + buf*KCH;

        #pragma unroll
        for (int kf = 0; kf < 2; kf++){
            int cr0 = kf*8 + q;
            int cr1 = kf*8 + q + 4;
            uint32_t ah[2][4], al[2][4];
            #pragma unroll
            for (int mf = 0; mf < 2; mf++){
                int kr = kw*32 + mf*16;
                ah[mf][0] = __float_as_uint(khb[cr0*KSTR + kr + g    ]);
                ah[mf][1] = __float_as_uint(khb[cr0*KSTR + kr + g + 8]);
                ah[mf][2] = __float_as_uint(khb[cr1*KSTR + kr + g    ]);
                ah[mf][3] = __float_as_uint(khb[cr1*KSTR + kr + g + 8]);
                al[mf][0] = __float_as_uint(klb[cr0*KSTR + kr + g    ]);
                al[mf][1] = __float_as_uint(klb[cr0*KSTR + kr + g + 8]);
                al[mf][2] = __float_as_uint(klb[cr1*KSTR + kr + g    ]);
                al[mf][3] = __float_as_uint(klb[cr1*KSTR + kr + g + 8]);
            }
            #pragma unroll
            for (int nf = 0; nf < 4; nf++){
                int col = qw*32 + nf*8 + g;
                uint32_t bh0 = __float_as_uint(qh[(c0+cr0)*QSTR + col]);
                uint32_t bh1 = __float_as_uint(qh[(c0+cr1)*QSTR + col]);
                uint32_t bl0 = __float_as_uint(ql[(c0+cr0)*QSTR + col]);
                uint32_t bl1 = __float_as_uint(ql[(c0+cr1)*QSTR + col]);
                #pragma unroll
                for (int mf = 0; mf < 2; mf++){
                    mma_tf32(acc[mf][nf], al[mf][0],al[mf][1],al[mf][2],al[mf][3], bh0,bh1);
                    mma_tf32(acc[mf][nf], ah[mf][0],ah[mf][1],ah[mf][2],ah[mf][3], bl0,bl1);
                    mma_tf32(acc[mf][nf], ah[mf][0],ah[mf][1],ah[mf][2],ah[mf][3], bh0,bh1);
                }
            }
        }

        if (c0i == 8){
            #pragma unroll
            for (int mf = 0; mf < 2; mf++){
                int keyA = l0 + kw*32 + mf*16 + g;
                int keyB = keyA + 8;
                #pragma unroll
                for (int nf = 0; nf < 4; nf++){
                    #pragma unroll
                    for (int p = 0; p < 2; p++){
                        int sl = nf*2 + p;
                        float vA = acc[mf][nf][p];
                        float vB = acc[mf][nf][2+p];
                        if (vA > bestv[sl]){ bestv[sl] = vA; besti[sl] = keyA; }
                        if (vB > bestv[sl]){ bestv[sl] = vB; besti[sl] = keyB; }
                    }
                }
            }
        }
    }

    __syncthreads();
    float* sv = kh;   // 2048 <= KCH
    float* si = kl;
    #pragma unroll
    for (int nf = 0; nf < 4; nf++)
        #pragma unroll
        for (int p = 0; p < 2; p++){
            int qcol = qw*32 + nf*8 + 2*q + p;
            int sl   = nf*2 + p;
            sv[qcol*32 + kw*8 + g] = bestv[sl];
            si[qcol*32 + kw*8 + g] = __int_as_float(besti[sl]);
        }
    __syncthreads();
    if (tid < 64){
        float bv = -FLT_MAX; int bi = 0x7fffffff;
        for (int t2 = 0; t2 < 32; t2++){
            float v  = sv[tid*32 + t2];
            int   ix = __float_as_int(si[tid*32 + t2]);
            if (v > bv || (v == bv && ix < bi)){ bv = v; bi = ix; }
        }
        int m = m0 + tid;
        mv[((size_t)half*BA + b)*6400 + m] = bv;
        mi[((size_t)half*BA + b)*6400 + m] = bi;
    }
}

// ---------------- merge two k-halves ----------------
__global__ void merge_kernel(const float* __restrict__ mv, const int* __restrict__ mi,
                             float* __restrict__ outp){
    int t = blockIdx.x*blockDim.x + threadIdx.x;
    if (t >= BA*6400) return;
    float v0 = mv[t], v1 = mv[BA*6400 + t];
    int   i0 = mi[t], i1 = mi[BA*6400 + t];
    float v = v0; int i = i0;
    if (v1 > v0){ v = v1; i = i1; }
    outp[t]             = v;
    outp[BA*6400 + t]   = (float)i;
}

extern "C" void kernel_launch(void* const* d_in, const int* in_sizes, int n_in,
                              void* d_out, int out_size){
    (void)in_sizes; (void)n_in; (void)out_size;
    const float* query = (const float*)d_in[0];
    const float* key   = (const float*)d_in[1];
    const float* w1 = (const float*)d_in[2];  const float* b1 = (const float*)d_in[3];
    const float* w2 = (const float*)d_in[4];  const float* b2 = (const float*)d_in[5];
    const float* w3 = (const float*)d_in[6];  const float* b3 = (const float*)d_in[7];
    const float* w4 = (const float*)d_in[8];  const float* b4 = (const float*)d_in[9];
    const float* wm = (const float*)d_in[10]; const float* bm = (const float*)d_in[11];
    float* out = (float*)d_out;

    float *up, *bufA, *bufB, *feat, *P, *wT, *mv;
    uint32_t *Ph, *Pl;
    int *mi;
    cudaGetSymbolAddress((void**)&up,     g_up);
    cudaGetSymbolAddress((void**)&bufA,   g_bufA);
    cudaGetSymbolAddress((void**)&bufB,   g_bufB);
    cudaGetSymbolAddress((void**)&feat,   g_feat);
    cudaGetSymbolAddress((void**)&P,      g_P);
    cudaGetSymbolAddress((void**)&Ph,     g_Ph);
    cudaGetSymbolAddress((void**)&Pl,     g_Pl);
    cudaGetSymbolAddress((void**)&wT,     g_wT);
    cudaGetSymbolAddress((void**)&mv,     g_mv);
    cudaGetSymbolAddress((void**)&mi,     g_mi);

    size_t conv_smem = CONV_SMEM_FLOATS * sizeof(float);   // ~80 KB
    cudaFuncSetAttribute(conv3x3_tf32_kernel,
                         cudaFuncAttributeMaxDynamicSharedMemorySize, (int)conv_smem);

    transw_all_kernel<<<(259776+255)/256,256>>>(w1, w2, w3, w4, wT);
    upsample_both_kernel<<<(2*BA*3*320*320+255)/256,256>>>(query, key, up);

    conv3x3_kernel<<<dim3(5,160,4*1),256>>>(up,   wT+OFF_W1, b1, bufA, 3,  64, 320, 320);
    // conv2 tf32 remains overall launch #6 = ncu capture slot
    conv3x3_tf32_kernel<<<dim3(4,160,4*1),256,conv_smem>>>(bufA, wT+OFF_W2, b2, bufB, 64, 64, 320, 320);
    maxpool2_kernel<<<(4*64*160*160+255)/256,256>>>(bufB, bufA, 4*64*160*160, 160, 160);
    conv3x3_tf32_kernel<<<dim3(2,80,4*2),256,conv_smem>>>(bufA, wT+OFF_W3, b3, bufB, 64, 128, 160, 160);
    conv3x3_tf32_kernel<<<dim3(2,80,4*2),256,conv_smem>>>(bufB, wT+OFF_W4, b4, bufA, 128,128, 160, 160);
    maxpool2_kernel<<<(4*128*80*80+255)/256,256>>>(bufA, bufB, 4*128*80*80, 80, 80);
    conv1x1_leaky_kernel<<<(4*16*6400+255)/256,256>>>(bufB, wm, bm, feat);

    patches_norm_kernel<<<(4*6400+255)/256,256>>>(feat, P);
    psplit_kernel<<<(4*144*6400+255)/256,256>>>(P, Ph, Pl);

    size_t match_smem = (2*144*QSTR + 4*KCH) * sizeof(float);   // ~110 KB
    cudaFuncSetAttribute(match_tf32_kernel,
                         cudaFuncAttributeMaxDynamicSharedMemorySize, (int)match_smem);
    match_tf32_kernel<<<dim3(100,BA,2),256,match_smem>>>(Ph, Pl, mv, mi);
    merge_kernel<<<(BA*6400+255)/256,256>>>(mv, mi, out);
}

// round 17
// speedup vs baseline: 1.3694x; 1.0334x over previous
#include <cuda_runtime.h>
#include <cstdint>
#include <cfloat>
#include <math.h>

#define BA 2
#define A_COEF (-0.75f)

__constant__ float c_mean[3] = {0.485f, 0.456f, 0.406f};
__constant__ float c_std[3]  = {0.229f, 0.224f, 0.225f};

// ---------------- scratch (static device memory) ----------------
__device__ float    g_up   [4*3*320*320];
__device__ float    g_bufA [4*64*320*320];
__device__ float    g_bufB [4*64*320*320];
__device__ float    g_feat [4*16*80*80];
__device__ uint32_t g_Ph   [4*144*6400];
__device__ uint32_t g_Pl   [4*144*6400];
__device__ float    g_wT   [259776];
__device__ float    g_mv   [2*BA*6400];
__device__ int      g_mi   [2*BA*6400];

#define OFF_W1 0
#define OFF_W2 1728
#define OFF_W3 38592
#define OFF_W4 112320

__device__ __forceinline__ float cubicw(float d){
    d = fabsf(d);
    if (d <= 1.f) return ((A_COEF + 2.f)*d - (A_COEF + 3.f))*d*d + 1.f;
    if (d < 2.f)  return A_COEF*(((d - 5.f)*d + 8.f)*d - 4.f);
    return 0.f;
}

// ---------------- tf32 helpers ----------------
__device__ __forceinline__ void split_tf32(float x, uint32_t& hi, uint32_t& lo){
    uint32_t h;
    asm("cvt.rna.tf32.f32 %0, %1;" : "=r"(h) : "f"(x));
    float l = x - __uint_as_float(h);
    uint32_t lr;
    asm("cvt.rna.tf32.f32 %0, %1;" : "=r"(lr) : "f"(l));
    hi = h; lo = lr;
}

__device__ __forceinline__ void mma_tf32(float* c,
        uint32_t a0, uint32_t a1, uint32_t a2, uint32_t a3,
        uint32_t b0, uint32_t b1){
    asm volatile("mma.sync.aligned.m16n8k8.row.col.f32.tf32.tf32.f32 "
        "{%0,%1,%2,%3}, {%4,%5,%6,%7}, {%8,%9}, {%0,%1,%2,%3};"
        : "+f"(c[0]),"+f"(c[1]),"+f"(c[2]),"+f"(c[3])
        : "r"(a0),"r"(a1),"r"(a2),"r"(a3), "r"(b0),"r"(b1));
}

// ---------------- cp.async helpers ----------------
__device__ __forceinline__ uint32_t smem_u32(const void* p){
    return (uint32_t)__cvta_generic_to_shared(p);
}
__device__ __forceinline__ void cp_async4(uint32_t saddr, const void* gptr, bool pred){
    int sz = pred ? 4 : 0;
    asm volatile("cp.async.ca.shared.global [%0], [%1], 4, %2;\n"
        :: "r"(saddr), "l"(gptr), "r"(sz));
}
#define CP_COMMIT()  asm volatile("cp.async.commit_group;\n" ::)
#define CP_WAIT0()   asm volatile("cp.async.wait_group 0;\n" ::)

// ---------------- merged weight transpose ----------------
__global__ void transw_all_kernel(const float* __restrict__ w1, const float* __restrict__ w2,
                                  const float* __restrict__ w3, const float* __restrict__ w4,
                                  float* __restrict__ wT){
    int t = blockIdx.x*blockDim.x + threadIdx.x;
    if (t >= 259776) return;
    const float* w; int CO, CI, base;
    if (t < 38592){
        if (t < 1728){ w = w1; CO = 64;  CI = 3;   base = OFF_W1; }
        else         { w = w2; CO = 64;  CI = 64;  base = OFF_W2; }
    } else {
        if (t < 112320){ w = w3; CO = 128; CI = 64;  base = OFF_W3; }
        else           { w = w4; CO = 128; CI = 128; base = OFF_W4; }
    }
    int loc = t - base;
    int co  = loc / (CI*9);
    int r   = loc - co*(CI*9);
    wT[base + r*CO + co] = w[loc];
}

// ---------------- merged: sub_mean + bicubic upsample x2 for BOTH paths ----------------
__global__ void upsample_both_kernel(const float* __restrict__ query,
                                     const float* __restrict__ key,
                                     float* __restrict__ dst){
    const int HALF = BA*3*320*320;
    int t = blockIdx.x*blockDim.x + threadIdx.x;
    if (t >= 2*HALF) return;
    int path = t / HALF;
    int r    = t - path*HALF;
    int ox = r % 320;
    int oy = (r / 320) % 320;
    int c  = (r / (320*320)) % 3;
    int b  = r / (320*320*3);

    const int Hs = 160, Ws = 160;
    float sy = (float)((double)(Hs-1) / 319.0);
    float sx = (float)((double)(Ws-1) / 319.0);
    float cy = (float)oy * sy;
    float cx = (float)ox * sx;
    float fy = floorf(cy), fx = floorf(cx);
    float tv = cy - fy,    tu = cx - fx;
    int iy = (int)fy, ix = (int)fx;

    float wy[4] = {cubicw(tv+1.f), cubicw(tv), cubicw(tv-1.f), cubicw(tv-2.f)};
    float wx[4] = {cubicw(tu+1.f), cubicw(tu), cubicw(tu-1.f), cubicw(tu-2.f)};

    float mean = c_mean[c], stdv = c_std[c];
    const float* qp = query + ((size_t)b*3 + c)*Hs*Ws;
    const float* kp = key   + ((size_t)b*3 + c)*320*320;

    float acc = 0.f;
    #pragma unroll
    for (int j = 0; j < 4; j++){
        int xx = ix - 1 + j;
        xx = xx < 0 ? 0 : (xx > Ws-1 ? Ws-1 : xx);
        float colsum = 0.f;
        #pragma unroll
        for (int i = 0; i < 4; i++){
            int yy = iy - 1 + i;
            yy = yy < 0 ? 0 : (yy > Hs-1 ? Hs-1 : yy);
            float s;
            if (path == 0){
                s = qp[yy*Ws + xx];
            } else {
                const float* p = kp + (yy*2)*320 + xx*2;
                s = (p[0] + p[1] + p[320] + p[321]) / 4.0f;
            }
            float v = (s - mean) / stdv;
            colsum += wy[i]*v;
        }
        acc += wx[j]*colsum;
    }
    dst[(size_t)path*HALF + r] = acc;
}

// ---------------- conv3x3 FFMA (CI=3 first layer) ----------------
__global__ __launch_bounds__(256)
void conv3x3_kernel(const float* __restrict__ in, const float* __restrict__ wT,
                    const float* __restrict__ bias, float* __restrict__ out,
                    int CI, int CO, int H, int W){
    __shared__ float insm[8*4*72];
    __shared__ float wsm [72*64];

    int tid = threadIdx.x;
    int tx = tid & 15;
    int ty = tid >> 4;
    int x0 = blockIdx.x * 64;
    int y0 = blockIdx.y * 2;
    int cog = CO >> 6;
    int b   = blockIdx.z / cog;
    int co0 = (blockIdx.z % cog) << 6;

    float acc[4][2][4];
    #pragma unroll
    for (int i = 0; i < 4; i++)
        #pragma unroll
        for (int r = 0; r < 2; r++)
            #pragma unroll
            for (int j = 0; j < 4; j++) acc[i][r][j] = 0.f;

    const float* inb = in + (size_t)b*CI*H*W;

    for (int ci0 = 0; ci0 < CI; ci0 += 8){
        int cn = CI - ci0; if (cn > 8) cn = 8;
        __syncthreads();
        int nin = cn*264;
        for (int s = tid; s < nin; s += 256){
            int ci  = s / 264;
            int rem = s - ci*264;
            int r   = rem / 66;
            int xx  = rem - r*66;
            int gy = y0 + r - 1;
            int gx = x0 + xx - 1;
            float v = 0.f;
            if (gy >= 0 && gy < H && gx >= 0 && gx < W)
                v = inb[((size_t)(ci0+ci)*H + gy)*W + gx];
            insm[(ci*4 + r)*72 + xx] = v;
        }
        int kk = cn*9;
        for (int s = tid; s < kk*64; s += 256){
            int k  = s >> 6;
            int co = s & 63;
            wsm[k*64 + co] = wT[((size_t)ci0*9 + k)*CO + co0 + co];
        }
        __syncthreads();

        float accc[4][2][4];
        #pragma unroll
        for (int i = 0; i < 4; i++)
            #pragma unroll
            for (int r = 0; r < 2; r++)
                #pragma unroll
                for (int j = 0; j < 4; j++) accc[i][r][j] = 0.f;

        for (int ci = 0; ci < cn; ci++){
            #pragma unroll
            for (int dy = 0; dy < 3; dy++){
                const float* ipa = &insm[(ci*4 + dy)*72 + tx*4];
                float a6[6], b6[6];
                #pragma unroll
                for (int u = 0; u < 6; u++){ a6[u] = ipa[u]; b6[u] = ipa[72+u]; }
                #pragma unroll
                for (int dx = 0; dx < 3; dx++){
                    float4 wv = *(const float4*)&wsm[(ci*9 + dy*3 + dx)*64 + ty*4];
                    #pragma unroll
                    for (int j = 0; j < 4; j++){
                        float ia = a6[dx + j];
                        float ib = b6[dx + j];
                        accc[0][0][j] += wv.x * ia;  accc[0][1][j] += wv.x * ib;
                        accc[1][0][j] += wv.y * ia;  accc[1][1][j] += wv.y * ib;
                        accc[2][0][j] += wv.z * ia;  accc[2][1][j] += wv.z * ib;
                        accc[3][0][j] += wv.w * ia;  accc[3][1][j] += wv.w * ib;
                    }
                }
            }
        }
        #pragma unroll
        for (int i = 0; i < 4; i++)
            #pragma unroll
            for (int r = 0; r < 2; r++)
                #pragma unroll
                for (int j = 0; j < 4; j++) acc[i][r][j] += accc[i][r][j];
    }

    #pragma unroll
    for (int i = 0; i < 4; i++){
        int co = co0 + ty*4 + i;
        float bv = bias[co];
        #pragma unroll
        for (int r = 0; r < 2; r++){
            #pragma unroll
            for (int j = 0; j < 4; j++){
                int x = x0 + tx*4 + j;
                if (x < W){
                    float v = acc[i][r][j] + bv;
                    out[(((size_t)b*CO + co)*H + (y0+r))*W + x] = fmaxf(v, 0.f);
                }
            }
        }
    }
}

// ---------------- conv3x3 3xTF32, 2 rows/block, cp.async pipelined, 2 CTAs/SM ----------------
// pool=0: write relu(acc+bias) at (y0..y0+1, x..x+1) to HxW output
// pool=1: write relu(max4(acc)+bias) at (y0/2, x/2) to (H/2)x(W/2) output (bit-exact fusion)
#define ISM_N   (8*4*84)
#define STG_N   (8*4*82)
#define WSM_N   (9*8*65)
#define CONV_SMEM_FLOATS (2*ISM_N + 2*STG_N + 2*WSM_N)

__global__ __launch_bounds__(256, 2)
void conv3x3_tf32_kernel(const float* __restrict__ in, const float* __restrict__ wT,
                         const float* __restrict__ bias, float* __restrict__ out,
                         int CI, int CO, int H, int W, int pool){
    extern __shared__ float csm[];
    float* ismh = csm;
    float* isml = ismh + ISM_N;
    float* stg  = isml + ISM_N;
    float* wsm  = stg + 2*STG_N;

    int tid  = threadIdx.x;
    int warp = tid >> 5, lane = tid & 31;
    int wm = warp & 3;
    int wn = warp >> 2;
    int g  = lane >> 2;
    int q  = lane & 3;

    int x0 = blockIdx.x * 80;
    int y0 = blockIdx.y * 2;
    int cog = CO >> 6;
    int b   = blockIdx.z / cog;
    int co0 = (blockIdx.z % cog) << 6;

    const float* inb = in + (size_t)b*CI*H*W;
    uint32_t stg_base = smem_u32(stg);
    uint32_t wsm_base = smem_u32(wsm);

    float cacc[2][5][4];
    #pragma unroll
    for (int r = 0; r < 2; r++)
        #pragma unroll
        for (int nt = 0; nt < 5; nt++)
            #pragma unroll
            for (int i = 0; i < 4; i++) cacc[r][nt][i] = 0.f;

    int nch = CI >> 3;

    auto issue_chunk = [&](int ci0, int buf){
        for (int s = tid; s < STG_N; s += 256){
            int ci  = s / 328;
            int rem = s - ci*328;
            int r   = rem / 82;
            int col = rem - r*82;
            int gy = y0 + r - 1;
            int gx = x0 + col - 1;
            bool ok = (gy >= 0 && gy < H && gx >= 0 && gx < W);
            const float* gp = ok ? (inb + ((size_t)(ci0+ci)*H + gy)*W + gx) : inb;
            cp_async4(stg_base + (uint32_t)(buf*STG_N + s)*4u, gp, ok);
        }
        for (int s = tid; s < 9*8*64; s += 256){
            int tap = s >> 9;
            int rem = s & 511;
            int ci  = rem >> 6;
            int co  = rem & 63;
            cp_async4(wsm_base + (uint32_t)(buf*WSM_N + (tap*8+ci)*65 + co)*4u,
                      wT + ((size_t)(ci0+ci)*9 + tap)*CO + co0 + co, true);
        }
        CP_COMMIT();
    };

    issue_chunk(0, 0);

    for (int c = 0; c < nch; c++){
        int buf = c & 1;
        CP_WAIT0();
        __syncthreads();

        const float* sb = stg + buf*STG_N;
        for (int s = tid; s < STG_N; s += 256){
            int ci  = s / 328;
            int rem = s - ci*328;
            int r   = rem / 82;
            int col = rem - r*82;
            uint32_t h, l;
            split_tf32(sb[s], h, l);
            ismh[(ci*4 + r)*84 + col] = __uint_as_float(h);
            isml[(ci*4 + r)*84 + col] = __uint_as_float(l);
        }
        __syncthreads();

        if (c + 1 < nch) issue_chunk((c+1)*8, buf^1);

        const float* wp = wsm + buf*WSM_N;
        #pragma unroll
        for (int dy = 0; dy < 3; dy++){
            #pragma unroll
            for (int dx = 0; dx < 3; dx++){
                int tap = dy*3 + dx;
                float a0 = wp[(tap*8 + q  )*65 + wm*16 + g    ];
                float a1 = wp[(tap*8 + q  )*65 + wm*16 + g + 8];
                float a2 = wp[(tap*8 + q+4)*65 + wm*16 + g    ];
                float a3 = wp[(tap*8 + q+4)*65 + wm*16 + g + 8];
                uint32_t ah0,al0,ah1,al1,ah2,al2,ah3,al3;
                split_tf32(a0, ah0, al0);
                split_tf32(a1, ah1, al1);
                split_tf32(a2, ah2, al2);
                split_tf32(a3, ah3, al3);
                #pragma unroll
                for (int r = 0; r < 2; r++){
                    #pragma unroll
                    for (int nt = 0; nt < 5; nt++){
                        int col = wn*40 + nt*8 + g + dx;
                        int i0 = ( q   *4 + r + dy)*84 + col;
                        int i1 = ((q+4)*4 + r + dy)*84 + col;
                        uint32_t bh0 = __float_as_uint(ismh[i0]);
                        uint32_t bh1 = __float_as_uint(ismh[i1]);
                        uint32_t bl0 = __float_as_uint(isml[i0]);
                        uint32_t bl1 = __float_as_uint(isml[i1]);
                        mma_tf32(cacc[r][nt], al0,al1,al2,al3, bh0,bh1);
                        mma_tf32(cacc[r][nt], ah0,ah1,ah2,ah3, bl0,bl1);
                        mma_tf32(cacc[r][nt], ah0,ah1,ah2,ah3, bh0,bh1);
                    }
                }
            }
        }
    }

    int coA = co0 + wm*16 + g;
    int coB = coA + 8;
    float bvA = bias[coA], bvB = bias[coB];
    if (!pool){
        #pragma unroll
        for (int r = 0; r < 2; r++){
            float* outA = out + (((size_t)b*CO + coA)*H + (y0+r))*W;
            float* outB = out + (((size_t)b*CO + coB)*H + (y0+r))*W;
            #pragma unroll
            for (int nt = 0; nt < 5; nt++){
                int x = x0 + wn*40 + nt*8 + 2*q;
                outA[x  ] = fmaxf(cacc[r][nt][0] + bvA, 0.f);
                outA[x+1] = fmaxf(cacc[r][nt][1] + bvA, 0.f);
                outB[x  ] = fmaxf(cacc[r][nt][2] + bvB, 0.f);
                outB[x+1] = fmaxf(cacc[r][nt][3] + bvB, 0.f);
            }
        }
    } else {
        // fused 2x2 maxpool: max tree identical to standalone maxpool (r0c0,r0c1),(r1c0,r1c1)
        int Hp = H >> 1, Wp = W >> 1;
        int yp = y0 >> 1;
        float* outA = out + (((size_t)b*CO + coA)*Hp + yp)*Wp;
        float* outB = out + (((size_t)b*CO + coB)*Hp + yp)*Wp;
        #pragma unroll
        for (int nt = 0; nt < 5; nt++){
            int xp = (x0 + wn*40 + nt*8 + 2*q) >> 1;
            float mA = fmaxf(fmaxf(cacc[0][nt][0], cacc[0][nt][1]),
                             fmaxf(cacc[1][nt][0], cacc[1][nt][1]));
            float mB = fmaxf(fmaxf(cacc[0][nt][2], cacc[0][nt][3]),
                             fmaxf(cacc[1][nt][2], cacc[1][nt][3]));
            outA[xp] = fmaxf(mA + bvA, 0.f);
            outB[xp] = fmaxf(mB + bvB, 0.f);
        }
    }
}

// ---------------- 1x1 map conv (128 -> 16) + LeakyReLU(0.2), B=4 ----------------
__global__ void conv1x1_leaky_kernel(const float* __restrict__ in, const float* __restrict__ w,
                                     const float* __restrict__ bias, float* __restrict__ out){
    int t = blockIdx.x*blockDim.x + threadIdx.x;
    if (t >= 4*16*6400) return;
    int px = t % 6400;
    int co = (t / 6400) % 16;
    int b  = t / (6400*16);
    const float* ip = in + (size_t)b*128*6400 + px;
    const float* wp = w + co*128;
    float s = 0.f;
    for (int c0 = 0; c0 < 128; c0 += 16){
        float sc = 0.f;
        #pragma unroll
        for (int ci = 0; ci < 16; ci++) sc += ip[(size_t)(c0+ci)*6400] * wp[c0+ci];
        s += sc;
    }
    s += bias[co];
    out[t] = s > 0.f ? s : 0.2f*s;
}

// ---------------- unfold + L2 normalize + tf32 split fused: feat -> Ph/Pl ----------------
__global__ void patches_split_kernel(const float* __restrict__ f,
                                     uint32_t* __restrict__ Ph, uint32_t* __restrict__ Pl){
    int t = blockIdx.x*blockDim.x + threadIdx.x;
    if (t >= 4*6400) return;
    int m = t % 6400;
    int b = t / 6400;
    int y = m / 80, x = m % 80;
    int ry[3], rx[3];
    #pragma unroll
    for (int i = 0; i < 3; i++){
        int yy = y + i - 1; ry[i] = yy < 0 ? -yy : (yy > 79 ? 158 - yy : yy);
        int xx = x + i - 1; rx[i] = xx < 0 ? -xx : (xx > 79 ? 158 - xx : xx);
    }
    const float* fb = f + (size_t)b*16*6400;
    float ss = 0.f;
    for (int c = 0; c < 16; c++){
        const float* fc = fb + c*6400;
        float sc = 0.f;
        #pragma unroll
        for (int i = 0; i < 3; i++)
            #pragma unroll
            for (int j = 0; j < 3; j++){
                float v = fc[ry[i]*80 + rx[j]];
                sc += v*v;
            }
        ss += sc;
    }
    float nrm = fmaxf(sqrtf(ss), 1e-12f);
    uint32_t* Phb = Ph + (size_t)b*144*6400;
    uint32_t* Plb = Pl + (size_t)b*144*6400;
    for (int c = 0; c < 16; c++){
        const float* fc = fb + c*6400;
        #pragma unroll
        for (int i = 0; i < 3; i++)
            #pragma unroll
            for (int j = 0; j < 3; j++){
                uint32_t h, l;
                split_tf32(fc[ry[i]*80 + rx[j]] / nrm, h, l);
                size_t o = (size_t)(c*9 + i*3 + j)*6400 + m;
                Phb[o] = h;
                Plb[o] = l;
            }
    }
}

// ---------------- cosine-sim 3xTF32 mma v3: cp.async double-buffered K tiles ----------------
#define QSTR 68
#define KSTR 132
#define KCH  (16*KSTR)
__global__ __launch_bounds__(256)
void match_tf32_kernel(const uint32_t* __restrict__ Ph, const uint32_t* __restrict__ Pl,
                       float* __restrict__ mv, int* __restrict__ mi){
    extern __shared__ float dsm[];
    float* qh = dsm;
    float* ql = qh + 144*QSTR;
    float* kh = ql + 144*QSTR;
    float* kl = kh + 2*KCH;

    int b    = blockIdx.y;
    int half = blockIdx.z;
    int m0   = blockIdx.x * 64;
    int tid  = threadIdx.x;
    int warp = tid >> 5, lane = tid & 31;
    int kw = warp & 3;
    int qw = warp >> 2;
    int g  = lane >> 2;
    int q  = lane & 3;

    const uint32_t* Qhb = Ph + (size_t)b*144*6400;
    const uint32_t* Qlb = Pl + (size_t)b*144*6400;
    const uint32_t* Khb = Ph + (size_t)(2+b)*144*6400;
    const uint32_t* Klb = Pl + (size_t)(2+b)*144*6400;

    uint32_t kh_base = smem_u32(kh);
    uint32_t kl_base = smem_u32(kl);
    int lbeg = half*3200;

    auto issue_kchunk = [&](int idx, int buf){
        int l0 = lbeg + (idx/9)*128;
        int c0 = (idx - (idx/9)*9)*16;
        for (int s = tid; s < 16*128; s += 256){
            int cc = s >> 7, ll = s & 127;
            size_t go = (size_t)(c0+cc)*6400 + l0 + ll;
            uint32_t so = (uint32_t)(buf*KCH + cc*KSTR + ll)*4u;
            cp_async4(kh_base + so, Khb + go, true);
            cp_async4(kl_base + so, Klb + go, true);
        }
        CP_COMMIT();
    };

    issue_kchunk(0, 0);

    for (int s = tid; s < 144*64; s += 256){
        int c = s >> 6, mm = s & 63;
        qh[c*QSTR + mm] = __uint_as_float(Qhb[(size_t)c*6400 + m0 + mm]);
        ql[c*QSTR + mm] = __uint_as_float(Qlb[(size_t)c*6400 + m0 + mm]);
    }

    float bestv[8];
    int   besti[8];
    #pragma unroll
    for (int i = 0; i < 8; i++){ bestv[i] = -FLT_MAX; besti[i] = 0; }

    float acc[2][4][4];

    for (int idx = 0; idx < 225; idx++){
        int buf  = idx & 1;
        int lt   = idx / 9;
        int c0i  = idx - lt*9;
        int l0   = lbeg + lt*128;
        int c0   = c0i*16;

        CP_WAIT0();
        __syncthreads();

        if (idx + 1 < 225) issue_kchunk(idx+1, buf^1);

        if (c0i == 0){
            #pragma unroll
            for (int mf = 0; mf < 2; mf++)
                #pragma unroll
                for (int nf = 0; nf < 4; nf++)
                    #pragma unroll
                    for (int i = 0; i < 4; i++) acc[mf][nf][i] = 0.f;
        }

        const float* khb = kh + buf*KCH;
        const float* klb = kl + buf*KCH;

        #pragma unroll
        for (int kf = 0; kf < 2; kf++){
            int cr0 = kf*8 + q;
            int cr1 = kf*8 + q + 4;
            uint32_t ah[2][4], al[2][4];
            #pragma unroll
            for (int mf = 0; mf < 2; mf++){
                int kr = kw*32 + mf*16;
                ah[mf][0] = __float_as_uint(khb[cr0*KSTR + kr + g    ]);
                ah[mf][1] = __float_as_uint(khb[cr0*KSTR + kr + g + 8]);
                ah[mf][2] = __float_as_uint(khb[cr1*KSTR + kr + g    ]);
                ah[mf][3] = __float_as_uint(khb[cr1*KSTR + kr + g + 8]);
                al[mf][0] = __float_as_uint(klb[cr0*KSTR + kr + g    ]);
                al[mf][1] = __float_as_uint(klb[cr0*KSTR + kr + g + 8]);
                al[mf][2] = __float_as_uint(klb[cr1*KSTR + kr + g    ]);
                al[mf][3] = __float_as_uint(klb[cr1*KSTR + kr + g + 8]);
            }
            #pragma unroll
            for (int nf = 0; nf < 4; nf++){
                int col = qw*32 + nf*8 + g;
                uint32_t bh0 = __float_as_uint(qh[(c0+cr0)*QSTR + col]);
                uint32_t bh1 = __float_as_uint(qh[(c0+cr1)*QSTR + col]);
                uint32_t bl0 = __float_as_uint(ql[(c0+cr0)*QSTR + col]);
                uint32_t bl1 = __float_as_uint(ql[(c0+cr1)*QSTR + col]);
                #pragma unroll
                for (int mf = 0; mf < 2; mf++){
                    mma_tf32(acc[mf][nf], al[mf][0],al[mf][1],al[mf][2],al[mf][3], bh0,bh1);
                    mma_tf32(acc[mf][nf], ah[mf][0],ah[mf][1],ah[mf][2],ah[mf][3], bl0,bl1);
                    mma_tf32(acc[mf][nf], ah[mf][0],ah[mf][1],ah[mf][2],ah[mf][3], bh0,bh1);
                }
            }
        }

        if (c0i == 8){
            #pragma unroll
            for (int mf = 0; mf < 2; mf++){
                int keyA = l0 + kw*32 + mf*16 + g;
                int keyB = keyA + 8;
                #pragma unroll
                for (int nf = 0; nf < 4; nf++){
                    #pragma unroll
                    for (int p = 0; p < 2; p++){
                        int sl = nf*2 + p;
                        float vA = acc[mf][nf][p];
                        float vB = acc[mf][nf][2+p];
                        if (vA > bestv[sl]){ bestv[sl] = vA; besti[sl] = keyA; }
                        if (vB > bestv[sl]){ bestv[sl] = vB; besti[sl] = keyB; }
                    }
                }
            }
        }
    }

    __syncthreads();
    float* sv = kh;
    float* si = kl;
    #pragma unroll
    for (int nf = 0; nf < 4; nf++)
        #pragma unroll
        for (int p = 0; p < 2; p++){
            int qcol = qw*32 + nf*8 + 2*q + p;
            int sl   = nf*2 + p;
            sv[qcol*32 + kw*8 + g] = bestv[sl];
            si[qcol*32 + kw*8 + g] = __int_as_float(besti[sl]);
        }
    __syncthreads();
    if (tid < 64){
        float bv = -FLT_MAX; int bi = 0x7fffffff;
        for (int t2 = 0; t2 < 32; t2++){
            float v  = sv[tid*32 + t2];
            int   ix = __float_as_int(si[tid*32 + t2]);
            if (v > bv || (v == bv && ix < bi)){ bv = v; bi = ix; }
        }
        int m = m0 + tid;
        mv[((size_t)half*BA + b)*6400 + m] = bv;
        mi[((size_t)half*BA + b)*6400 + m] = bi;
    }
}

// ---------------- merge two k-halves ----------------
__global__ void merge_kernel(const float* __restrict__ mv, const int* __restrict__ mi,
                             float* __restrict__ outp){
    int t = blockIdx.x*blockDim.x + threadIdx.x;
    if (t >= BA*6400) return;
    float v0 = mv[t], v1 = mv[BA*6400 + t];
    int   i0 = mi[t], i1 = mi[BA*6400 + t];
    float v = v0; int i = i0;
    if (v1 > v0){ v = v1; i = i1; }
    outp[t]             = v;
    outp[BA*6400 + t]   = (float)i;
}

extern "C" void kernel_launch(void* const* d_in, const int* in_sizes, int n_in,
                              void* d_out, int out_size){
    (void)in_sizes; (void)n_in; (void)out_size;
    const float* query = (const float*)d_in[0];
    const float* key   = (const float*)d_in[1];
    const float* w1 = (const float*)d_in[2];  const float* b1 = (const float*)d_in[3];
    const float* w2 = (const float*)d_in[4];  const float* b2 = (const float*)d_in[5];
    const float* w3 = (const float*)d_in[6];  const float* b3 = (const float*)d_in[7];
    const float* w4 = (const float*)d_in[8];  const float* b4 = (const float*)d_in[9];
    const float* wm = (const float*)d_in[10]; const float* bm = (const float*)d_in[11];
    float* out = (float*)d_out;

    float *up, *bufA, *bufB, *feat, *wT, *mv;
    uint32_t *Ph, *Pl;
    int *mi;
    cudaGetSymbolAddress((void**)&up,     g_up);
    cudaGetSymbolAddress((void**)&bufA,   g_bufA);
    cudaGetSymbolAddress((void**)&bufB,   g_bufB);
    cudaGetSymbolAddress((void**)&feat,   g_feat);
    cudaGetSymbolAddress((void**)&Ph,     g_Ph);
    cudaGetSymbolAddress((void**)&Pl,     g_Pl);
    cudaGetSymbolAddress((void**)&wT,     g_wT);
    cudaGetSymbolAddress((void**)&mv,     g_mv);
    cudaGetSymbolAddress((void**)&mi,     g_mi);

    size_t conv_smem = CONV_SMEM_FLOATS * sizeof(float);   // ~80 KB
    cudaFuncSetAttribute(conv3x3_tf32_kernel,
                         cudaFuncAttributeMaxDynamicSharedMemorySize, (int)conv_smem);

    transw_all_kernel<<<(259776+255)/256,256>>>(w1, w2, w3, w4, wT);
    upsample_both_kernel<<<(2*BA*3*320*320+255)/256,256>>>(query, key, up);

    // conv1 FFMA: up(320^2,3) -> bufA(320^2,64)
    conv3x3_kernel<<<dim3(5,160,4*1),256>>>(up, wT+OFF_W1, b1, bufA, 3, 64, 320, 320);
    // conv2 tf32 + fused maxpool: bufA(320^2,64) -> bufB(160^2,64)   [launch #6 = ncu slot]
    conv3x3_tf32_kernel<<<dim3(4,160,4*1),256,conv_smem>>>(bufA, wT+OFF_W2, b2, bufB, 64, 64, 320, 320, 1);
    // conv3 tf32: bufB(160^2,64) -> bufA(160^2,128)
    conv3x3_tf32_kernel<<<dim3(2,80,4*2),256,conv_smem>>>(bufB, wT+OFF_W3, b3, bufA, 64, 128, 160, 160, 0);
    // conv4 tf32 + fused maxpool: bufA(160^2,128) -> bufB(80^2,128)
    conv3x3_tf32_kernel<<<dim3(2,80,4*2),256,conv_smem>>>(bufA, wT+OFF_W4, b4, bufB, 128, 128, 160, 160, 1);
    // 1x1 conv: bufB(80^2,128) -> feat(80^2,16)
    conv1x1_leaky_kernel<<<(4*16*6400+255)/256,256>>>(bufB, wm, bm, feat);

    // patches + normalize + tf32 split (direct to Ph/Pl, P never materialized)
    patches_split_kernel<<<(4*6400+255)/256,256>>>(feat, Ph, Pl);

    size_t match_smem = (2*144*QSTR + 4*KCH) * sizeof(float);   // ~110 KB
    cudaFuncSetAttribute(match_tf32_kernel,
                         cudaFuncAttributeMaxDynamicSharedMemorySize, (int)match_smem);
    match_tf32_kernel<<<dim3(100,BA,2),256,match_smem>>>(Ph, Pl, mv, mi);
    merge_kernel<<<(BA*6400+255)/256,256>>>(mv, mi, out);
}